// round 14
// baseline (speedup 1.0000x reference)
#include <cuda_runtime.h>
#include <cuda_bf16.h>
#include <math.h>
#include <cstdint>

// ---------------------------------------------------------------------------
// SSMXLSTMFusion: D=512, S=3, BATCH=256, H=8, HD=64
// Round 14: 128x128 block tiles (warp 32x64) - halves B-fragment smem traffic
// per mma and doubles mma per sync window. 2-stage cp.async (80KB/CTA,
// 2 CTAs/SM). R12 task graph: chain 2x8 terms (A^1..A^8, KT=16), persistent
// chain + tail kernels, pre-split bf16 hi/lo operands.
// ---------------------------------------------------------------------------

#define DD    512
#define BB    256
#define SS    3
typedef __nv_bfloat16 bf16;

// ------------------------- fp32 scratch ------------------------------------
__device__ float g_h1   [BB*DD];
__device__ float g_delta[BB];
__device__ float g_bx   [BB*DD];
__device__ float g_U    [4*BB*8*DD];          // 4 split-K planes
__device__ float g_gA   [SS*BB*4*DD];
__device__ float g_gB   [SS*BB*4*DD];
__device__ float g_kvp  [2*SS*BB*2*DD];
__device__ float g_qp   [8*BB*DD];            // 8 split-K planes
__device__ float g_part [22*BB*DD];           // hssm 0-7, ctx 8-15, hnew 16-21
__device__ float g_pvec [DD];

// ------------------------- bf16 hi/lo planes --------------------------------
__device__ bf16 g_xh[BB*DD],          g_xl[BB*DD];
__device__ bf16 g_hph[BB*DD],         g_hpl[BB*DD];
__device__ bf16 g_lhh[SS*BB*DD],      g_lhl[SS*BB*DD];
__device__ bf16 g_w1h[DD*DD],         g_w1l[DD*DD];
__device__ bf16 g_bmh[DD*DD],         g_bml[DD*DD];
__device__ bf16 g_wihh[SS*4*DD*DD],   g_wihl[SS*4*DD*DD];
__device__ bf16 g_whhh[SS*4*DD*DD],   g_whhl[SS*4*DD*DD];
__device__ bf16 g_aiwh[3*DD*DD],      g_aiwl[3*DD*DD];
__device__ bf16 g_pwh[DD*5*DD],       g_pwl[DD*5*DD];
__device__ bf16 g_wpowh[8*DD*DD],     g_wpowl[8*DD*DD];    // A^1..A^8
__device__ bf16 g_ath[DD*DD],         g_atl[DD*DD];
__device__ bf16 g_a2th[DD*DD],        g_a2tl[DD*DD];
__device__ bf16 g_a4th[DD*DD],        g_a4tl[DD*DD];
__device__ bf16 g_aoth[DD*DD],        g_aotl[DD*DD];
__device__ bf16 g_mh[DD*DD],          g_ml[DD*DD];
__device__ bf16 g_th[BB*DD],          g_tl[BB*DD];
__device__ bf16 g_hsh[BB*DD],         g_hsl[BB*DD];
__device__ bf16 g_hnh[SS*BB*DD],      g_hnl[SS*BB*DD];
__device__ bf16 g_cxh[BB*DD],         g_cxl[BB*DD];

__device__ volatile unsigned g_gen1; __device__ unsigned g_cnt1;
__device__ volatile unsigned g_gen2; __device__ unsigned g_cnt2;

// ========================= descriptors ======================================
struct GTask {
    const bf16 *Xhi, *Xlo, *Whi, *Wlo, *Wn2hi, *Wn2lo;
    const float* bias;
    float *C, *Cn2;
    bf16 *Chi, *Clo, *Cthi, *Ctlo;
    int ldX, ldW, ldC, ldCn2, ldCt;
    int K, kofs, nsplit, mtiles, blocks;
};
struct GTaskSet { GTask t[12]; int ntasks; };

struct STask { const float* src; bf16 *hi, *lo; int blocks; };
struct STaskSet { STask t[12]; int ntasks; };

#define NOSPLIT (1<<30)

// ========================= smem layout ======================================
// per stage: A_HI(128x80) A_LO B_HI(128x80) B_LO = 40960 B; 2 stages = 81920
#define RSB     80
#define OFF_AHI 0
#define OFF_ALO 10240
#define OFF_BHI 20480
#define OFF_BLO 30720
#define STAGE   40960
#define SMEM_SZ (2*STAGE)      // 81920 bytes

__device__ __forceinline__ uint32_t smem_to_u32(const void* p) {
    uint32_t a;
    asm("{ .reg .u64 t; cvta.to.shared.u64 t, %1; cvt.u32.u64 %0, t; }"
        : "=r"(a) : "l"(p));
    return a;
}

__device__ __forceinline__ uint32_t pk2(bf16 a, bf16 b) {
    uint16_t ua = *(uint16_t*)&a, ub = *(uint16_t*)&b;
    return (uint32_t)ua | ((uint32_t)ub << 16);
}

__device__ __forceinline__ void split8(float4 u, float4 v, uint4& hi, uint4& lo)
{
    float f[8] = {u.x,u.y,u.z,u.w,v.x,v.y,v.z,v.w};
    uint32_t h[4], l[4];
    #pragma unroll
    for (int i = 0; i < 4; i++) {
        bf16 b0 = __float2bfloat16_rn(f[2*i]);
        bf16 b1 = __float2bfloat16_rn(f[2*i+1]);
        bf16 r0 = __float2bfloat16_rn(f[2*i]   - __bfloat162float(b0));
        bf16 r1 = __float2bfloat16_rn(f[2*i+1] - __bfloat162float(b1));
        h[i] = pk2(b0, b1);
        l[i] = pk2(r0, r1);
    }
    hi = make_uint4(h[0], h[1], h[2], h[3]);
    lo = make_uint4(l[0], l[1], l[2], l[3]);
}

__device__ __forceinline__ void ldm_x4(uint32_t* r, uint32_t addr) {
    asm volatile("ldmatrix.sync.aligned.m8n8.x4.shared.b16 {%0,%1,%2,%3}, [%4];"
        : "=r"(r[0]), "=r"(r[1]), "=r"(r[2]), "=r"(r[3]) : "r"(addr));
}

__device__ __forceinline__ void mma_bf16(float* c, const uint32_t* a, const uint32_t* b)
{
    asm volatile(
        "mma.sync.aligned.m16n8k16.row.col.f32.bf16.bf16.f32 "
        "{%0,%1,%2,%3}, {%4,%5,%6,%7}, {%8,%9}, {%0,%1,%2,%3};"
        : "+f"(c[0]), "+f"(c[1]), "+f"(c[2]), "+f"(c[3])
        : "r"(a[0]), "r"(a[1]), "r"(a[2]), "r"(a[3]), "r"(b[0]), "r"(b[1]));
}

#define CP16(saddr, gaddr) \
    asm volatile("cp.async.cg.shared.global [%0], [%1], 16;" \
        :: "r"(saddr), "l"(gaddr) : "memory")

__device__ __forceinline__ void grid_barrier(volatile unsigned* gen,
                                             unsigned* cnt, unsigned total)
{
    __syncthreads();
    if (threadIdx.x == 0) {
        unsigned mygen = *gen;
        __threadfence();
        unsigned t = atomicAdd(cnt, 1u);
        if (t == total - 1) {
            *cnt = 0;
            __threadfence();
            *gen = mygen + 1;
        } else {
            while (*gen == mygen) { __nanosleep(32); }
            __threadfence();
        }
    }
    __syncthreads();
}

// ------------------------- GEMM tile (device) --------------------------------
// issue one 32-K chunk: A 128 rows hi+lo, B 128 rows hi+lo (8 cp16/thread)
__device__ __forceinline__ void issue_chunk(const GTask& T, uint32_t smb,
    int m0, int n0, int tid, int k0, int stage)
{
    const uint32_t sb = smb + (uint32_t)(stage * STAGE);
    #pragma unroll
    for (int j = 0; j < 4; j++) {
        int o  = tid + j*256;
        int pl = o >> 9;
        int r  = (o >> 2) & 127;
        int s  = o & 3;
        const bf16* g = (pl ? T.Xlo : T.Xhi) + (long)(m0 + r) * T.ldX + k0 + s*8;
        uint32_t sa = sb + (uint32_t)(pl*10240 + r*80 + s*16);
        CP16(sa, g);
    }
    #pragma unroll
    for (int j = 0; j < 4; j++) {
        int o  = tid + j*256;
        int pl = o >> 9;
        int r  = (o >> 2) & 127;
        int s  = o & 3;
        int ng = n0 + r;
        const bf16* w;
        if (ng >= T.nsplit)
            w = (pl ? T.Wn2lo : T.Wn2hi) + (long)(ng - T.nsplit) * T.ldW;
        else
            w = (pl ? T.Wlo : T.Whi) + (long)ng * T.ldW;
        uint32_t sa = sb + (uint32_t)(20480 + pl*10240 + r*80 + s*16);
        CP16(sa, w + k0 + s*8);
    }
    asm volatile("cp.async.commit_group;" ::: "memory");
}

// 128x128 tile, 256 threads (8 warps: 4m x 2n), warp tile 32x64.
__device__ void gemm_tile(const GTask& T, int b, char* smem)
{
    const int m0 = (b % T.mtiles) * 128;
    const int n0 = (b / T.mtiles) * 128;

    const int tid = threadIdx.x;
    const int lid = tid & 31;
    const int wid = tid >> 5;
    const int m_base = (wid & 3) * 32;
    const int n_base = (wid >> 2) * 64;
    const int gid = lid >> 2;
    const int tig = lid & 3;
    const int g  = lid >> 3;
    const int ig = lid & 7;

    const uint32_t smb = smem_to_u32(smem);
    const uint32_t a_ad = smb + (uint32_t)((m_base + (g&1)*8 + ig) * RSB + (g>>1)*16);
    const uint32_t b_ad = smb + (uint32_t)((n_base + (g>>1)*8 + ig) * RSB + (g&1)*16);

    float acc[2][8][4];
    #pragma unroll
    for (int i = 0; i < 2; i++)
        #pragma unroll
        for (int j = 0; j < 8; j++)
            #pragma unroll
            for (int k = 0; k < 4; k++) acc[i][j][k] = 0.0f;

    const int nc = T.K >> 5;

    issue_chunk(T, smb, m0, n0, tid, T.kofs, 0);
    if (nc > 1) issue_chunk(T, smb, m0, n0, tid, T.kofs + 32, 1);

    for (int c = 0; c < nc; c++) {
        if (c + 1 < nc)
            asm volatile("cp.async.wait_group 1;" ::: "memory");
        else
            asm volatile("cp.async.wait_group 0;" ::: "memory");
        __syncthreads();

        const uint32_t sb = (uint32_t)((c & 1) * STAGE);
        #pragma unroll
        for (int ks = 0; ks < 2; ks++) {
            const uint32_t kb = sb + ks * 32;
            uint32_t ahi[2][4], alo[2][4];
            #pragma unroll
            for (int mt = 0; mt < 2; mt++) {
                ldm_x4(ahi[mt], a_ad + OFF_AHI + mt*16*RSB + kb);
                ldm_x4(alo[mt], a_ad + OFF_ALO + mt*16*RSB + kb);
            }
            #pragma unroll
            for (int np = 0; np < 4; np++) {
                uint32_t rh[4], rl[4];
                ldm_x4(rh, b_ad + OFF_BHI + np*16*RSB + kb);
                ldm_x4(rl, b_ad + OFF_BLO + np*16*RSB + kb);
                #pragma unroll
                for (int mt = 0; mt < 2; mt++)
                    #pragma unroll
                    for (int j = 0; j < 2; j++) {
                        mma_bf16(acc[mt][2*np+j], ahi[mt], &rh[2*j]);
                        mma_bf16(acc[mt][2*np+j], ahi[mt], &rl[2*j]);
                        mma_bf16(acc[mt][2*np+j], alo[mt], &rh[2*j]);
                    }
            }
        }
        __syncthreads();
        if (c + 2 < nc)
            issue_chunk(T, smb, m0, n0, tid, T.kofs + (c+2)*32, c & 1);
    }

    #pragma unroll
    for (int mt = 0; mt < 2; mt++) {
        #pragma unroll
        for (int nt = 0; nt < 8; nt++) {
            int n = n0 + n_base + nt*8 + tig*2;
            #pragma unroll
            for (int half = 0; half < 2; half++) {
                int mm = m0 + m_base + mt*16 + gid + half*8;
                float v0 = acc[mt][nt][half*2];
                float v1 = acc[mt][nt][half*2 + 1];
                if (T.Cn2 && n >= T.nsplit) {
                    int nn = n - T.nsplit;
                    *(float2*)(T.Cn2 + (long)mm*T.ldCn2 + nn) = make_float2(v0, v1);
                } else {
                    if (T.bias) { v0 += T.bias[n]; v1 += T.bias[n+1]; }
                    if (T.C)
                        *(float2*)(T.C + (long)mm*T.ldC + n) = make_float2(v0, v1);
                    if (T.Chi) {
                        bf16 h0 = __float2bfloat16_rn(v0);
                        bf16 h1 = __float2bfloat16_rn(v1);
                        bf16 l0 = __float2bfloat16_rn(v0 - __bfloat162float(h0));
                        bf16 l1 = __float2bfloat16_rn(v1 - __bfloat162float(h1));
                        *(uint32_t*)(T.Chi + (long)mm*T.ldC + n) = pk2(h0, h1);
                        *(uint32_t*)(T.Clo + (long)mm*T.ldC + n) = pk2(l0, l1);
                        if (T.Cthi) {
                            T.Cthi[(long)n*T.ldCt + mm]       = h0;
                            T.Ctlo[(long)n*T.ldCt + mm]       = l0;
                            T.Cthi[(long)(n+1)*T.ldCt + mm]   = h1;
                            T.Ctlo[(long)(n+1)*T.ldCt + mm]   = l1;
                        }
                    }
                }
            }
        }
    }
}

// ========================= batched GEMM launch ==============================
__global__ void __launch_bounds__(256, 2)
gemm_mma(GTaskSet ts)
{
    extern __shared__ char smem[];
    int b = blockIdx.x, ti = 0;
    while (b >= ts.t[ti].blocks) { b -= ts.t[ti].blocks; ti++; }
    gemm_tile(ts.t[ti], b, smem);
}

// ========================= prep: split + transposes =========================
__global__ void prep_kernel(STaskSet ts, int split_blocks,
                            const float* __restrict__ A,
                            bf16* __restrict__ athi, bf16* __restrict__ atlo,
                            const float* __restrict__ B,
                            bf16* __restrict__ bthi, bf16* __restrict__ btlo)
{
    int b = blockIdx.x;
    if (b < split_blocks) {
        int ti = 0;
        while (b >= ts.t[ti].blocks) { b -= ts.t[ti].blocks; ti++; }
        const STask S = ts.t[ti];
        long idx = ((long)b * 256 + threadIdx.x) * 8;
        float4 u = *(const float4*)(S.src + idx);
        float4 v = *(const float4*)(S.src + idx + 4);
        uint4 hi, lo;
        split8(u, v, hi, lo);
        *(uint4*)(S.hi + idx) = hi;
        *(uint4*)(S.lo + idx) = lo;
        return;
    }
    int tb = b - split_blocks;
    int z  = tb >> 8;
    int rem = tb & 255;
    int bx = (rem & 15) * 32, by = (rem >> 4) * 32;
    int tx = threadIdx.x & 31, ty = threadIdx.x >> 5;
    __shared__ float t[32][33];
    const float* src = z ? B : A;
    bf16* dh = z ? bthi : athi;
    bf16* dl = z ? btlo : atlo;
    int x = bx + tx;
    #pragma unroll
    for (int i = 0; i < 32; i += 8) {
        int y = by + ty + i;
        t[ty + i][tx] = src[(long)y*DD + x];
    }
    __syncthreads();
    int xo = by + tx;
    #pragma unroll
    for (int i = 0; i < 32; i += 8) {
        int yo = bx + ty + i;
        float v = t[tx][ty + i];
        bf16 h = __float2bfloat16_rn(v);
        dh[(long)yo*DD + xo] = h;
        dl[(long)yo*DD + xo] = __float2bfloat16_rn(v - __bfloat162float(h));
    }
}

// ========================= S1 fused ==========================================
__device__ __forceinline__ float sigf(float x) { return 1.0f / (1.0f + expf(-x)); }

__global__ void s1_kernel(const float* __restrict__ h1,
                          const float* __restrict__ dn_g,
                          const float* __restrict__ dn_beta,
                          const float* __restrict__ w2,
                          const float* __restrict__ b2,
                          float* __restrict__ delta,
                          const float* __restrict__ proj_w,
                          const float* __restrict__ aob,
                          const float* __restrict__ proj_b,
                          float* __restrict__ pvec,
                          const float* __restrict__ gA,
                          const float* __restrict__ gB,
                          const float* __restrict__ bih,
                          const float* __restrict__ bhh,
                          const float* __restrict__ lstm_c,
                          const float* __restrict__ decays,
                          float* __restrict__ h_new,
                          float* __restrict__ c_new,
                          bf16* __restrict__ hnh,
                          bf16* __restrict__ hnl)
{
    int blk = blockIdx.x, t = threadIdx.x;
    if (blk < 256) {
        __shared__ float red[256];
        int row = blk;
        const float* r = h1 + (long)row * DD;
        float x0 = r[t], x1 = r[t + 256];
        red[t] = x0 + x1; __syncthreads();
        for (int o = 128; o > 0; o >>= 1) { if (t < o) red[t] += red[t+o]; __syncthreads(); }
        float mean = red[0] * (1.0f/DD);
        __syncthreads();
        float d0 = x0 - mean, d1 = x1 - mean;
        red[t] = d0*d0 + d1*d1; __syncthreads();
        for (int o = 128; o > 0; o >>= 1) { if (t < o) red[t] += red[t+o]; __syncthreads(); }
        float inv = rsqrtf(red[0] * (1.0f/DD) + 1e-5f);
        __syncthreads();
        float y0 = d0 * inv * dn_g[t]     + dn_beta[t];
        float y1 = d1 * inv * dn_g[t+256] + dn_beta[t+256];
        y0 = 0.5f * y0 * (1.0f + erff(y0 * 0.70710678118654752f));
        y1 = 0.5f * y1 * (1.0f + erff(y1 * 0.70710678118654752f));
        red[t] = y0*w2[t] + y1*w2[t+256]; __syncthreads();
        for (int o = 128; o > 0; o >>= 1) { if (t < o) red[t] += red[t+o]; __syncthreads(); }
        if (t == 0) {
            float z = red[0] + b2[0];
            delta[row] = (z > 20.0f) ? z : log1pf(expf(z));
        }
    } else if (blk < 768) {
        __shared__ float red[256];
        int row = blk - 256;
        const float* r = proj_w + (long)row * 2560 + 512;
        red[t] = r[t]*aob[t] + r[t+256]*aob[t+256];
        __syncthreads();
        for (int o = 128; o > 0; o >>= 1) { if (t < o) red[t] += red[t+o]; __syncthreads(); }
        if (t == 0) pvec[row] = proj_b[row] + red[0];
    } else {
        int idx = (blk - 768) * 256 + t;
        int s = idx / (BB*DD);
        int r = idx - s * (BB*DD);
        int b = r >> 9;
        int d = r & 511;
        long gbase = ((long)s * BB + b) * 2048;
        const float* a = gA + gbase;
        const float* h = gB + gbase;
        const float* bi = bih + s*2048;
        const float* bh = bhh + s*2048;
        float ip = a[d]      + h[d]      + bi[d]      + bh[d];
        float fp = a[512+d]  + h[512+d]  + bi[512+d]  + bh[512+d];
        float gp = a[1024+d] + h[1024+d] + bi[1024+d] + bh[1024+d];
        float op = a[1536+d] + h[1536+d] + bi[1536+d] + bh[1536+d];
        float i_g = sigf(ip);
        float f_g = sigf(fp);
        float g_g = tanhf(gp);
        float o_g = sigf(op);
        float c   = lstm_c[idx];
        float craw = f_g * c + i_g * g_g;
        float hn   = o_g * tanhf(craw);
        float dec  = decays[s];
        h_new[idx] = hn;
        c_new[idx] = dec * c + (1.0f - dec) * craw;
        bf16 hh = __float2bfloat16_rn(hn);
        hnh[idx] = hh;
        hnl[idx] = __float2bfloat16_rn(hn - __bfloat162float(hh));
    }
}

// ========================= persistent chain kernel ===========================
// 256 blocks. 2 iters x 8 terms. GEMM: N=4096, split-K4 -> 256 tile-jobs
// (kz = blk>>6, tile = blk&63: 2m x 32n). y register-resident (2 elts).
__global__ void __launch_bounds__(256, 2)
chain_kernel(const bf16* __restrict__ hph, const bf16* __restrict__ hpl,
             const bf16* __restrict__ wpowh, const bf16* __restrict__ wpowl,
             float* __restrict__ U,
             bf16* __restrict__ th, bf16* __restrict__ tl,
             const float* __restrict__ delta,
             const float* __restrict__ h_prev,
             const float* __restrict__ bx,
             float* __restrict__ out_hssm,
             bf16* __restrict__ hsh, bf16* __restrict__ hsl)
{
    extern __shared__ char smem[];
    const int tid = threadIdx.x;
    const long PU = (long)BB * 8 * DD;
    const long idx0 = ((long)blockIdx.x * 256 + tid) * 2;
    const int row = (int)(idx0 >> 9);
    const int col = (int)(idx0 & 511);
    const float dval = delta[row];

    float y[2];
    y[0] = h_prev[idx0];
    y[1] = h_prev[idx0 + 1];

    for (int iter = 0; iter < 2; iter++) {
        {
            int kz   = blockIdx.x >> 6;       // 0..3
            int tile = blockIdx.x & 63;       // 2m x 32n
            GTask T = {};
            T.Xhi = iter ? th : hph;  T.Xlo = iter ? tl : hpl;  T.ldX = DD;
            T.Whi = wpowh;            T.Wlo = wpowl;            T.ldW = DD;
            T.C = U + (long)kz * PU;  T.ldC = 8*DD;
            T.K = 128; T.kofs = kz*128; T.nsplit = NOSPLIT; T.mtiles = 2;
            gemm_tile(T, tile, smem);
        }
        grid_barrier(&g_gen1, &g_cnt1, 256);

        const int k0 = iter * 8;
        const float* u0 = U + (long)row * 4096 + col;
        float c = 1.0f, tlast[2] = {0.0f, 0.0f};
        for (int j = 0; j < 8; j++) {
            c *= dval / (float)(k0 + j + 1);
            #pragma unroll
            for (int e = 0; e < 2; e++) {
                float u = ((u0[j*512 + e] + u0[PU + j*512 + e])
                         + u0[2*PU + j*512 + e]) + u0[3*PU + j*512 + e];
                float term = c * u;
                tlast[e] = term;
                y[e] += term;
            }
        }
        if (iter == 0) {
            #pragma unroll
            for (int e = 0; e < 2; e++) {
                bf16 h = __float2bfloat16_rn(tlast[e]);
                th[idx0 + e] = h;
                tl[idx0 + e] = __float2bfloat16_rn(tlast[e] - __bfloat162float(h));
            }
            grid_barrier(&g_gen1, &g_cnt1, 256);
        } else {
            #pragma unroll
            for (int e = 0; e < 2; e++) {
                float yy = y[e] + dval * bx[idx0 + e];
                out_hssm[idx0 + e] = yy;
                bf16 h = __float2bfloat16_rn(yy);
                hsh[idx0 + e] = h;
                hsl[idx0 + e] = __float2bfloat16_rn(yy - __bfloat162float(h));
            }
        }
    }
}

// ========================= persistent tail kernel ============================
// 256 blocks: [q sK8 (64) + hssm-proj sK8 (64)] -> barrier -> attn -> barrier
// -> [ctx@M sK8 (64)] -> barrier -> proj reduce(22) + LN.
__global__ void __launch_bounds__(256, 2)
tail_kernel(const bf16* __restrict__ hsh, const bf16* __restrict__ hsl,
            const bf16* __restrict__ aiwh, const bf16* __restrict__ aiwl,
            const bf16* __restrict__ pwh, const bf16* __restrict__ pwl,
            const bf16* __restrict__ mh, const bf16* __restrict__ ml,
            float* __restrict__ qp, float* __restrict__ kvp,
            float* __restrict__ part,
            const float* __restrict__ attn_in_b,
            bf16* __restrict__ cxh, bf16* __restrict__ cxl,
            const float* __restrict__ pvec,
            const float* __restrict__ pg, const float* __restrict__ pbe,
            float* __restrict__ out_y)
{
    extern __shared__ char smem[];
    const int tid = threadIdx.x;
    const int blk = blockIdx.x;

    // ---- phase A: q split-K8 (64 blk) + hssm-proj split-K8 (64 blk) ----
    if (blk < 128) {
        GTask T = {};
        T.nsplit = NOSPLIT; T.mtiles = 2; T.K = 64;
        T.Xhi = hsh; T.Xlo = hsl; T.ldX = DD;
        if (blk < 64) {
            int kz = blk >> 3;          // 0..7
            T.Whi = aiwh; T.Wlo = aiwl; T.ldW = DD;
            T.C = qp + (long)kz*BB*DD; T.ldC = DD; T.kofs = kz*64;
            gemm_tile(T, blk & 7, smem);
        } else {
            int b2 = blk - 64;
            int kz = b2 >> 3;
            T.Whi = pwh; T.Wlo = pwl; T.ldW = 5*DD;
            T.C = part + (long)kz*BB*DD; T.ldC = DD; T.kofs = kz*64;
            gemm_tile(T, b2 & 7, smem);
        }
    }
    grid_barrier(&g_gen2, &g_cnt2, 256);

    // ---- phase B: attention (block = batch) ----
    {
        int b    = blk;
        int warp = tid >> 5;
        int lane = tid & 31;
        const long QP = (long)BB*DD;
        const long KP = (long)SS*BB*2*DD;

        long qo = (long)b * DD + warp * 64;
        float q0 = attn_in_b[warp*64 + lane];
        float q1 = attn_in_b[warp*64 + lane + 32];
        #pragma unroll
        for (int p = 0; p < 8; p++) {
            q0 += qp[p*QP + qo + lane];
            q1 += qp[p*QP + qo + lane + 32];
        }

        float sc[SS];
        #pragma unroll
        for (int s = 0; s < SS; s++) {
            long ko = (long)(s*BB + b) * 1024 + warp * 64;
            float k0 = kvp[ko + lane]      + kvp[KP + ko + lane]
                     + attn_in_b[512 + warp*64 + lane];
            float k1 = kvp[ko + lane + 32] + kvp[KP + ko + lane + 32]
                     + attn_in_b[512 + warp*64 + lane + 32];
            float d = q0 * k0 + q1 * k1;
            #pragma unroll
            for (int o = 16; o > 0; o >>= 1) d += __shfl_xor_sync(0xffffffff, d, o);
            sc[s] = d * 0.125f;
        }
        float m = fmaxf(sc[0], fmaxf(sc[1], sc[2]));
        float e[SS], sum = 0.0f;
        #pragma unroll
        for (int s = 0; s < SS; s++) { e[s] = expf(sc[s] - m); sum += e[s]; }
        float inv = 1.0f / sum;

        float c0 = 0.0f, c1 = 0.0f;
        #pragma unroll
        for (int s = 0; s < SS; s++) {
            long vo = (long)(s*BB + b) * 1024 + 512 + warp * 64;
            float v0 = kvp[vo + lane]      + kvp[KP + vo + lane]
                     + attn_in_b[1024 + warp*64 + lane];
            float v1 = kvp[vo + lane + 32] + kvp[KP + vo + lane + 32]
                     + attn_in_b[1024 + warp*64 + lane + 32];
            float w = e[s] * inv;
            c0 += w * v0;
            c1 += w * v1;
        }
        long o0 = (long)b * DD + warp*64 + lane;
        bf16 h0 = __float2bfloat16_rn(c0);
        bf16 h1 = __float2bfloat16_rn(c1);
        cxh[o0]      = h0;
        cxl[o0]      = __float2bfloat16_rn(c0 - __bfloat162float(h0));
        cxh[o0 + 32] = h1;
        cxl[o0 + 32] = __float2bfloat16_rn(c1 - __bfloat162float(h1));
    }
    grid_barrier(&g_gen2, &g_cnt2, 256);

    // ---- phase C: ctx @ M split-K8 (64 blk) -> part planes 8..15 ----
    if (blk < 64) {
        int kz = blk >> 3;
        GTask T = {};
        T.Xhi = cxh; T.Xlo = cxl; T.ldX = DD;
        T.Whi = mh; T.Wlo = ml; T.ldW = DD;
        T.C = part + (long)(8+kz)*BB*DD; T.ldC = DD;
        T.K = 64; T.kofs = kz*64; T.nsplit = NOSPLIT; T.mtiles = 2;
        gemm_tile(T, blk & 7, smem);
    }
    grid_barrier(&g_gen2, &g_cnt2, 256);

    // ---- phase D: proj reduce (22 planes) + LN ----
    {
        float* red = (float*)smem;
        int row = blk, t = tid;
        long o0 = (long)row*DD + t, o1 = o0 + 256;
        const long PL = (long)BB*DD;
        float x0 = pvec[t], x1 = pvec[t+256];
        #pragma unroll
        for (int p = 0; p < 22; p++) { x0 += part[p*PL + o0]; x1 += part[p*PL + o1]; }

        red[t] = x0 + x1; __syncthreads();
        for (int o = 128; o > 0; o >>= 1) { if (t < o) red[t] += red[t+o]; __syncthreads(); }
        float mean = red[0] * (1.0f/DD);
        __syncthreads();

        float d0 = x0 - mean, d1 = x1 - mean;
        red[t] = d0*d0 + d1*d1; __syncthreads();
        for (int o = 128; o > 0; o >>= 1) { if (t < o) red[t] += red[t+o]; __syncthreads(); }
        float inv = rsqrtf(red[0] * (1.0f/DD) + 1e-5f);

        out_y[o0] = d0 * inv * pg[t]     + pbe[t];
        out_y[o1] = d1 * inv * pg[t+256] + pbe[t+256];
    }
}

// ---------------------------------------------------------------------------
static inline GTask mk_task(const bf16* Xhi, const bf16* Xlo, int ldX,
                            const bf16* Whi, const bf16* Wlo, int ldW,
                            float* C, int ldC, int K, int kofs,
                            int mtiles, int ntiles)
{
    GTask t = {};
    t.Xhi = Xhi; t.Xlo = Xlo; t.ldX = ldX;
    t.Whi = Whi; t.Wlo = Wlo; t.ldW = ldW;
    t.C = C; t.ldC = ldC;
    t.K = K; t.kofs = kofs; t.nsplit = NOSPLIT;
    t.mtiles = mtiles; t.blocks = mtiles*ntiles;
    return t;
}

extern "C" void kernel_launch(void* const* d_in, const int* in_sizes, int n_in,
                              void* d_out, int out_size)
{
    (void)in_sizes; (void)n_in; (void)out_size;

    const float* x        = (const float*)d_in[0];
    const float* h_prev   = (const float*)d_in[1];
    const float* lstm_h   = (const float*)d_in[2];
    const float* lstm_c   = (const float*)d_in[3];
    const float* A        = (const float*)d_in[4];
    const float* Bm       = (const float*)d_in[5];
    const float* dn_w1    = (const float*)d_in[6];
    const float* dn_b1    = (const float*)d_in[7];
    const float* dn_g     = (const float*)d_in[8];
    const float* dn_beta  = (const float*)d_in[9];
    const float* dn_w2    = (const float*)d_in[10];
    const float* dn_b2    = (const float*)d_in[11];
    const float* lstm_wih = (const float*)d_in[12];
    const float* lstm_whh = (const float*)d_in[13];
    const float* lstm_bih = (const float*)d_in[14];
    const float* lstm_bhh = (const float*)d_in[15];
    const float* decays   = (const float*)d_in[16];
    const float* attn_in_w  = (const float*)d_in[17];
    const float* attn_in_b  = (const float*)d_in[18];
    const float* attn_out_w = (const float*)d_in[19];
    const float* attn_out_b = (const float*)d_in[20];
    const float* proj_w   = (const float*)d_in[21];
    const float* proj_b   = (const float*)d_in[22];
    const float* proj_g   = (const float*)d_in[23];
    const float* proj_beta= (const float*)d_in[24];

    float* out = (float*)d_out;
    float* out_y    = out;
    float* out_hssm = out + BB*DD;
    float* out_hnew = out + 2*BB*DD;
    float* out_cnew = out + 2*BB*DD + SS*BB*DD;

    float *p_h1, *p_delta, *p_bx, *p_U, *p_gA, *p_gB, *p_kvp, *p_qp, *p_part, *p_pvec;
    cudaGetSymbolAddress((void**)&p_h1,    g_h1);
    cudaGetSymbolAddress((void**)&p_delta, g_delta);
    cudaGetSymbolAddress((void**)&p_bx,    g_bx);
    cudaGetSymbolAddress((void**)&p_U,     g_U);
    cudaGetSymbolAddress((void**)&p_gA,    g_gA);
    cudaGetSymbolAddress((void**)&p_gB,    g_gB);
    cudaGetSymbolAddress((void**)&p_kvp,   g_kvp);
    cudaGetSymbolAddress((void**)&p_qp,    g_qp);
    cudaGetSymbolAddress((void**)&p_part,  g_part);
    cudaGetSymbolAddress((void**)&p_pvec,  g_pvec);

    bf16 *xh,*xl,*hph,*hpl,*lhh,*lhl,*w1h,*w1l,*bmh,*bml,*wihh,*wihl,*whhh,*whhl,
         *aiwh,*aiwl,*pwh,*pwl,*wpowh,*wpowl,*ath,*atl,*a2th,*a2tl,*a4th,*a4tl,
         *aoth,*aotl,*mh,*ml,*th,*tl,*hsh,*hsl,*hnh,*hnl,*cxh,*cxl;
    cudaGetSymbolAddress((void**)&xh, g_xh);     cudaGetSymbolAddress((void**)&xl, g_xl);
    cudaGetSymbolAddress((void**)&hph, g_hph);   cudaGetSymbolAddress((void**)&hpl, g_hpl);
    cudaGetSymbolAddress((void**)&lhh, g_lhh);   cudaGetSymbolAddress((void**)&lhl, g_lhl);
    cudaGetSymbolAddress((void**)&w1h, g_w1h);   cudaGetSymbolAddress((void**)&w1l, g_w1l);
    cudaGetSymbolAddress((void**)&bmh, g_bmh);   cudaGetSymbolAddress((void**)&bml, g_bml);
    cudaGetSymbolAddress((void**)&wihh, g_wihh); cudaGetSymbolAddress((void**)&wihl, g_wihl);
    cudaGetSymbolAddress((void**)&whhh, g_whhh); cudaGetSymbolAddress((void**)&whhl, g_whhl);
    cudaGetSymbolAddress((void**)&aiwh, g_aiwh); cudaGetSymbolAddress((void**)&aiwl, g_aiwl);
    cudaGetSymbolAddress((void**)&pwh, g_pwh);   cudaGetSymbolAddress((void**)&pwl, g_pwl);
    cudaGetSymbolAddress((void**)&wpowh, g_wpowh); cudaGetSymbolAddress((void**)&wpowl, g_wpowl);
    cudaGetSymbolAddress((void**)&ath, g_ath);   cudaGetSymbolAddress((void**)&atl, g_atl);
    cudaGetSymbolAddress((void**)&a2th, g_a2th); cudaGetSymbolAddress((void**)&a2tl, g_a2tl);
    cudaGetSymbolAddress((void**)&a4th, g_a4th); cudaGetSymbolAddress((void**)&a4tl, g_a4tl);
    cudaGetSymbolAddress((void**)&aoth, g_aoth); cudaGetSymbolAddress((void**)&aotl, g_aotl);
    cudaGetSymbolAddress((void**)&mh, g_mh);     cudaGetSymbolAddress((void**)&ml, g_ml);
    cudaGetSymbolAddress((void**)&th, g_th);     cudaGetSymbolAddress((void**)&tl, g_tl);
    cudaGetSymbolAddress((void**)&hsh, g_hsh);   cudaGetSymbolAddress((void**)&hsl, g_hsl);
    cudaGetSymbolAddress((void**)&hnh, g_hnh);   cudaGetSymbolAddress((void**)&hnl, g_hnl);
    cudaGetSymbolAddress((void**)&cxh, g_cxh);   cudaGetSymbolAddress((void**)&cxl, g_cxl);

    cudaFuncSetAttribute(gemm_mma,
        cudaFuncAttributeMaxDynamicSharedMemorySize, SMEM_SZ);
    cudaFuncSetAttribute(chain_kernel,
        cudaFuncAttributeMaxDynamicSharedMemorySize, SMEM_SZ);
    cudaFuncSetAttribute(tail_kernel,
        cudaFuncAttributeMaxDynamicSharedMemorySize, SMEM_SZ);

    const long W2 = (long)DD*DD;
    const long KP = (long)SS*BB*2*DD;

    // ---- K1: split all operands + transposes ----
    {
        STaskSet st = {};
        auto add = [&](int i, const float* s, bf16* h, bf16* l, long n) {
            st.t[i] = { s, h, l, (int)(n / 2048) };
        };
        add(0, x,        xh,   xl,   (long)BB*DD);
        add(1, h_prev,   hph,  hpl,  (long)BB*DD);
        add(2, lstm_h,   lhh,  lhl,  (long)SS*BB*DD);
        add(3, dn_w1,    w1h,  w1l,  W2);
        add(4, Bm,       bmh,  bml,  W2);
        add(5, lstm_wih, wihh, wihl, (long)SS*4*W2);
        add(6, lstm_whh, whhh, whhl, (long)SS*4*W2);
        add(7, attn_in_w, aiwh, aiwl, 3*W2);
        add(8, proj_w,   pwh,  pwl,  5*W2);
        add(9, A,        wpowh, wpowl, W2);
        st.ntasks = 10;
        int total = 0;
        for (int i = 0; i < 10; i++) total += st.t[i].blocks;
        prep_kernel<<<total + 512, 256>>>(st, total,
            A, ath, atl, attn_out_w, aoth, aotl);
    }

    // ---- K2 (240 blocks): h1|bx, 6 lstm partials, A^2 (+A2T), M ----
    {
        GTaskSet ts = {};
        GTask t0 = mk_task(xh, xl, DD, w1h, w1l, DD, p_h1, DD, DD, 0, 2, 8);
        t0.bias = dn_b1; t0.Wn2hi = bmh; t0.Wn2lo = bml;
        t0.Cn2 = p_bx; t0.ldCn2 = DD; t0.nsplit = DD;
        ts.t[0] = t0;
        for (int s = 0; s < SS; s++) {
            ts.t[1+s] = mk_task(xh, xl, DD, wihh + (long)s*4*W2, wihl + (long)s*4*W2, DD,
                                p_gA + (long)s*BB*4*DD, 4*DD, DD, 0, 2, 16);
            ts.t[4+s] = mk_task(lhh + (long)s*BB*DD, lhl + (long)s*BB*DD, DD,
                                whhh + (long)s*4*W2, whhl + (long)s*4*W2, DD,
                                p_gB + (long)s*BB*4*DD, 4*DD, DD, 0, 2, 16);
        }
        GTask ta = mk_task(wpowh, wpowl, DD, ath, atl, DD, nullptr, DD, DD, 0, 4, 4);
        ta.Chi = wpowh + W2; ta.Clo = wpowl + W2;
        ta.Cthi = a2th; ta.Ctlo = a2tl; ta.ldCt = DD;
        ts.t[7] = ta;
        GTask tm = mk_task(pwh + 512, pwl + 512, 5*DD, aoth, aotl, DD,
                           nullptr, DD, DD, 0, 4, 4);
        tm.Chi = mh; tm.Clo = ml;
        ts.t[8] = tm;
        ts.ntasks = 9;
        gemm_mma<<<240, 256, SMEM_SZ>>>(ts);
    }

    // ---- K3: S1 fused ----
    s1_kernel<<<2304, 256>>>(p_h1, dn_g, dn_beta, dn_w2, dn_b2, p_delta,
                             proj_w, attn_out_b, proj_b, p_pvec,
                             p_gA, p_gB, lstm_bih, lstm_bhh, lstm_c, decays,
                             out_hnew, out_cnew, hnh, hnl);

    // ---- K4 (128 blocks): A^3, A^4 (+A4T), kv split-K-2 ----
    {
        GTaskSet ts = {};
        GTask t3 = mk_task(wpowh + W2, wpowl + W2, DD, ath, atl, DD,
                           nullptr, DD, DD, 0, 4, 4);
        t3.Chi = wpowh + 2*W2; t3.Clo = wpowl + 2*W2;
        ts.t[0] = t3;
        GTask t4 = mk_task(wpowh + W2, wpowl + W2, DD, a2th, a2tl, DD,
                           nullptr, DD, DD, 0, 4, 4);
        t4.Chi = wpowh + 3*W2; t4.Clo = wpowl + 3*W2;
        t4.Cthi = a4th; t4.Ctlo = a4tl; t4.ldCt = DD;
        ts.t[1] = t4;
        for (int kz = 0; kz < 2; kz++)
            ts.t[2+kz] = mk_task(hnh, hnl, DD, aiwh + W2, aiwl + W2, DD,
                                 p_kvp + (long)kz*KP, 2*DD, 256, kz*256, 6, 8);
        ts.ntasks = 4;
        gemm_mma<<<128, 256, SMEM_SZ>>>(ts);
    }

    // ---- K5 (112 blocks): A^5..A^8, h_new proj partials (planes 16..21) ----
    {
        GTaskSet ts = {};
        GTask t5 = mk_task(wpowh + 3*W2, wpowl + 3*W2, DD, ath, atl, DD,
                           nullptr, DD, DD, 0, 4, 4);
        t5.Chi = wpowh + 4*W2; t5.Clo = wpowl + 4*W2;
        ts.t[0] = t5;
        GTask t6 = mk_task(wpowh + 3*W2, wpowl + 3*W2, DD, a2th, a2tl, DD,
                           nullptr, DD, DD, 0, 4, 4);
        t6.Chi = wpowh + 5*W2; t6.Clo = wpowl + 5*W2;
        ts.t[1] = t6;
        GTask t7 = mk_task(wpowh + 2*W2, wpowl + 2*W2, DD, a4th, a4tl, DD,
                           nullptr, DD, DD, 0, 4, 4);
        t7.Chi = wpowh + 6*W2; t7.Clo = wpowl + 6*W2;
        ts.t[2] = t7;
        GTask t8 = mk_task(wpowh + 3*W2, wpowl + 3*W2, DD, a4th, a4tl, DD,
                           nullptr, DD, DD, 0, 4, 4);
        t8.Chi = wpowh + 7*W2; t8.Clo = wpowl + 7*W2;
        ts.t[3] = t8;
        int p = 0;
        for (int i = 0; i < SS; i++)
            for (int kz = 0; kz < 2; kz++, p++)
                ts.t[4+p] = mk_task(hnh + (long)i*BB*DD, hnl + (long)i*BB*DD, DD,
                                    pwh + 1024 + i*512, pwl + 1024 + i*512, 5*DD,
                                    p_part + (long)(16 + p)*BB*DD, DD,
                                    256, kz*256, 2, 4);
        ts.ntasks = 10;
        gemm_mma<<<112, 256, SMEM_SZ>>>(ts);
    }

    // ---- K6: persistent chain (2 iters x 8 terms, split-K4) ----
    chain_kernel<<<256, 256, SMEM_SZ>>>(hph, hpl, wpowh, wpowl, p_U, th, tl,
                                        p_delta, h_prev, p_bx,
                                        out_hssm, hsh, hsl);

    // ---- K7: persistent tail ----
    tail_kernel<<<256, 256, SMEM_SZ>>>(hsh, hsl, aiwh, aiwl, pwh, pwl, mh, ml,
                                       p_qp, p_kvp, p_part, attn_in_b,
                                       cxh, cxl, p_pvec, proj_g, proj_beta,
                                       out_y);
}

// round 15
// speedup vs baseline: 1.0797x; 1.0797x over previous
#include <cuda_runtime.h>
#include <cuda_bf16.h>
#include <math.h>
#include <cstdint>

// ---------------------------------------------------------------------------
// SSMXLSTMFusion: D=512, S=3, BATCH=256, H=8, HD=64
// Round 15: R12 base (128x64 tiles, 2 CTAs/SM, chain 2x8 KT=16) +
//  (1) one sync per chunk (trailing syncthreads removed; 3-stage safe),
//  (2) K5 uniform (hnew-proj tasks moved to tail phase A idle slots).
// ---------------------------------------------------------------------------

#define DD    512
#define BB    256
#define SS    3
typedef __nv_bfloat16 bf16;

// ------------------------- fp32 scratch ------------------------------------
__device__ float g_h1   [BB*DD];
__device__ float g_delta[BB];
__device__ float g_bx   [BB*DD];
__device__ float g_U    [2*BB*8*DD];
__device__ float g_gA   [SS*BB*4*DD];
__device__ float g_gB   [SS*BB*4*DD];
__device__ float g_kvp  [2*SS*BB*2*DD];
__device__ float g_qp   [4*BB*DD];
__device__ float g_part [14*BB*DD];           // hssm 0-3, ctx 4-7, hnew 8-13
__device__ float g_pvec [DD];

// ------------------------- bf16 hi/lo planes --------------------------------
__device__ bf16 g_xh[BB*DD],          g_xl[BB*DD];
__device__ bf16 g_hph[BB*DD],         g_hpl[BB*DD];
__device__ bf16 g_lhh[SS*BB*DD],      g_lhl[SS*BB*DD];
__device__ bf16 g_w1h[DD*DD],         g_w1l[DD*DD];
__device__ bf16 g_bmh[DD*DD],         g_bml[DD*DD];
__device__ bf16 g_wihh[SS*4*DD*DD],   g_wihl[SS*4*DD*DD];
__device__ bf16 g_whhh[SS*4*DD*DD],   g_whhl[SS*4*DD*DD];
__device__ bf16 g_aiwh[3*DD*DD],      g_aiwl[3*DD*DD];
__device__ bf16 g_pwh[DD*5*DD],       g_pwl[DD*5*DD];
__device__ bf16 g_wpowh[8*DD*DD],     g_wpowl[8*DD*DD];
__device__ bf16 g_ath[DD*DD],         g_atl[DD*DD];
__device__ bf16 g_a2th[DD*DD],        g_a2tl[DD*DD];
__device__ bf16 g_a4th[DD*DD],        g_a4tl[DD*DD];
__device__ bf16 g_aoth[DD*DD],        g_aotl[DD*DD];
__device__ bf16 g_mh[DD*DD],          g_ml[DD*DD];
__device__ bf16 g_th[BB*DD],          g_tl[BB*DD];
__device__ bf16 g_hsh[BB*DD],         g_hsl[BB*DD];
__device__ bf16 g_hnh[SS*BB*DD],      g_hnl[SS*BB*DD];
__device__ bf16 g_cxh[BB*DD],         g_cxl[BB*DD];

__device__ volatile unsigned g_gen1; __device__ unsigned g_cnt1;
__device__ volatile unsigned g_gen2; __device__ unsigned g_cnt2;

// ========================= descriptors ======================================
struct GTask {
    const bf16 *Xhi, *Xlo, *Whi, *Wlo, *Wn2hi, *Wn2lo;
    const float* bias;
    float *C, *Cn2;
    bf16 *Chi, *Clo, *Cthi, *Ctlo;
    int ldX, ldW, ldC, ldCn2, ldCt;
    int K, kofs, nsplit, mtiles, blocks;
};
struct GTaskSet { GTask t[12]; int ntasks; };

struct STask { const float* src; bf16 *hi, *lo; int blocks; };
struct STaskSet { STask t[12]; int ntasks; };

#define NOSPLIT (1<<30)

// ========================= smem layout ======================================
#define RSB     80
#define OFF_AHI 0
#define OFF_ALO 10240
#define OFF_BHI 20480
#define OFF_BLO 25600
#define STAGE   30720
#define SMEM_SZ (3*STAGE)      // 92160 bytes

__device__ __forceinline__ uint32_t smem_to_u32(const void* p) {
    uint32_t a;
    asm("{ .reg .u64 t; cvta.to.shared.u64 t, %1; cvt.u32.u64 %0, t; }"
        : "=r"(a) : "l"(p));
    return a;
}

__device__ __forceinline__ uint32_t pk2(bf16 a, bf16 b) {
    uint16_t ua = *(uint16_t*)&a, ub = *(uint16_t*)&b;
    return (uint32_t)ua | ((uint32_t)ub << 16);
}

__device__ __forceinline__ void split8(float4 u, float4 v, uint4& hi, uint4& lo)
{
    float f[8] = {u.x,u.y,u.z,u.w,v.x,v.y,v.z,v.w};
    uint32_t h[4], l[4];
    #pragma unroll
    for (int i = 0; i < 4; i++) {
        bf16 b0 = __float2bfloat16_rn(f[2*i]);
        bf16 b1 = __float2bfloat16_rn(f[2*i+1]);
        bf16 r0 = __float2bfloat16_rn(f[2*i]   - __bfloat162float(b0));
        bf16 r1 = __float2bfloat16_rn(f[2*i+1] - __bfloat162float(b1));
        h[i] = pk2(b0, b1);
        l[i] = pk2(r0, r1);
    }
    hi = make_uint4(h[0], h[1], h[2], h[3]);
    lo = make_uint4(l[0], l[1], l[2], l[3]);
}

__device__ __forceinline__ void ldm_x4(uint32_t* r, uint32_t addr) {
    asm volatile("ldmatrix.sync.aligned.m8n8.x4.shared.b16 {%0,%1,%2,%3}, [%4];"
        : "=r"(r[0]), "=r"(r[1]), "=r"(r[2]), "=r"(r[3]) : "r"(addr));
}

__device__ __forceinline__ void mma_bf16(float* c, const uint32_t* a, const uint32_t* b)
{
    asm volatile(
        "mma.sync.aligned.m16n8k16.row.col.f32.bf16.bf16.f32 "
        "{%0,%1,%2,%3}, {%4,%5,%6,%7}, {%8,%9}, {%0,%1,%2,%3};"
        : "+f"(c[0]), "+f"(c[1]), "+f"(c[2]), "+f"(c[3])
        : "r"(a[0]), "r"(a[1]), "r"(a[2]), "r"(a[3]), "r"(b[0]), "r"(b[1]));
}

#define CP16(saddr, gaddr) \
    asm volatile("cp.async.cg.shared.global [%0], [%1], 16;" \
        :: "r"(saddr), "l"(gaddr) : "memory")

__device__ __forceinline__ void grid_barrier(volatile unsigned* gen,
                                             unsigned* cnt, unsigned total)
{
    __syncthreads();
    if (threadIdx.x == 0) {
        unsigned mygen = *gen;
        __threadfence();
        unsigned t = atomicAdd(cnt, 1u);
        if (t == total - 1) {
            *cnt = 0;
            __threadfence();
            *gen = mygen + 1;
        } else {
            while (*gen == mygen) { __nanosleep(32); }
            __threadfence();
        }
    }
    __syncthreads();
}

// ------------------------- GEMM tile (device) --------------------------------
__device__ __forceinline__ void issue_chunk(const GTask& T, uint32_t smb,
    int m0, int n0, int tid, int k0, int stage)
{
    const uint32_t sb = smb + (uint32_t)(stage * STAGE);
    #pragma unroll
    for (int j = 0; j < 4; j++) {
        int o  = tid + j*256;
        int pl = o >> 9;
        int r  = (o >> 2) & 127;
        int s  = o & 3;
        const bf16* g = (pl ? T.Xlo : T.Xhi) + (long)(m0 + r) * T.ldX + k0 + s*8;
        uint32_t sa = sb + (uint32_t)(pl*10240 + r*80 + s*16);
        CP16(sa, g);
    }
    #pragma unroll
    for (int j = 0; j < 2; j++) {
        int o  = tid + j*256;
        int pl = o >> 8;
        int r  = (o >> 2) & 63;
        int s  = o & 3;
        int ng = n0 + r;
        const bf16* w;
        if (ng >= T.nsplit)
            w = (pl ? T.Wn2lo : T.Wn2hi) + (long)(ng - T.nsplit) * T.ldW;
        else
            w = (pl ? T.Wlo : T.Whi) + (long)ng * T.ldW;
        uint32_t sa = sb + (uint32_t)(20480 + pl*5120 + r*80 + s*16);
        CP16(sa, w + k0 + s*8);
    }
    asm volatile("cp.async.commit_group;" ::: "memory");
}

__device__ void gemm_tile(const GTask& T, int b, char* smem)
{
    const int m0 = (b % T.mtiles) * 128;
    const int n0 = (b / T.mtiles) * 64;

    const int tid = threadIdx.x;
    const int lid = tid & 31;
    const int wid = tid >> 5;
    const int m_base = (wid & 3) * 32;
    const int n_base = (wid >> 2) * 32;
    const int gid = lid >> 2;
    const int tig = lid & 3;
    const int g  = lid >> 3;
    const int ig = lid & 7;

    const uint32_t smb = smem_to_u32(smem);
    const uint32_t a_ad = smb + (uint32_t)((m_base + (g&1)*8 + ig) * RSB + (g>>1)*16);
    const uint32_t b_ad = smb + (uint32_t)((n_base + (g>>1)*8 + ig) * RSB + (g&1)*16);

    float acc[2][4][4];
    #pragma unroll
    for (int i = 0; i < 2; i++)
        #pragma unroll
        for (int j = 0; j < 4; j++)
            #pragma unroll
            for (int k = 0; k < 4; k++) acc[i][j][k] = 0.0f;

    const int nc = T.K >> 5;

    issue_chunk(T, smb, m0, n0, tid, T.kofs, 0);
    if (nc > 1) issue_chunk(T, smb, m0, n0, tid, T.kofs + 32, 1);

    for (int c = 0; c < nc; c++) {
        if (c + 1 < nc)
            asm volatile("cp.async.wait_group 1;" ::: "memory");
        else
            asm volatile("cp.async.wait_group 0;" ::: "memory");
        __syncthreads();

        if (c + 2 < nc)
            issue_chunk(T, smb, m0, n0, tid, T.kofs + (c+2)*32, (c+2)%3);

        const uint32_t sb = (uint32_t)((c % 3) * STAGE);
        #pragma unroll
        for (int ks = 0; ks < 2; ks++) {
            const uint32_t kb = sb + ks * 32;
            uint32_t ahi[2][4], alo[2][4], bhi[4][2], blo[4][2];
            #pragma unroll
            for (int mt = 0; mt < 2; mt++) {
                ldm_x4(ahi[mt], a_ad + OFF_AHI + mt*16*RSB + kb);
                ldm_x4(alo[mt], a_ad + OFF_ALO + mt*16*RSB + kb);
            }
            #pragma unroll
            for (int np = 0; np < 2; np++) {
                uint32_t r[4];
                ldm_x4(r, b_ad + OFF_BHI + np*16*RSB + kb);
                bhi[2*np][0] = r[0]; bhi[2*np][1] = r[1];
                bhi[2*np+1][0] = r[2]; bhi[2*np+1][1] = r[3];
                ldm_x4(r, b_ad + OFF_BLO + np*16*RSB + kb);
                blo[2*np][0] = r[0]; blo[2*np][1] = r[1];
                blo[2*np+1][0] = r[2]; blo[2*np+1][1] = r[3];
            }
            #pragma unroll
            for (int mt = 0; mt < 2; mt++)
                #pragma unroll
                for (int nt = 0; nt < 4; nt++) {
                    mma_bf16(acc[mt][nt], ahi[mt], bhi[nt]);
                    mma_bf16(acc[mt][nt], ahi[mt], blo[nt]);
                    mma_bf16(acc[mt][nt], alo[mt], bhi[nt]);
                }
        }
        // NOTE: no trailing __syncthreads — next iteration's top sync (after
        // wait_group) orders these fragment reads before the cp.async that
        // overwrites this stage (3-stage ring: overwrite happens 3 iters later).
    }

    #pragma unroll
    for (int mt = 0; mt < 2; mt++) {
        #pragma unroll
        for (int nt = 0; nt < 4; nt++) {
            int n = n0 + n_base + nt*8 + tig*2;
            #pragma unroll
            for (int half = 0; half < 2; half++) {
                int mm = m0 + m_base + mt*16 + gid + half*8;
                float v0 = acc[mt][nt][half*2];
                float v1 = acc[mt][nt][half*2 + 1];
                if (T.Cn2 && n >= T.nsplit) {
                    int nn = n - T.nsplit;
                    *(float2*)(T.Cn2 + (long)mm*T.ldCn2 + nn) = make_float2(v0, v1);
                } else {
                    if (T.bias) { v0 += T.bias[n]; v1 += T.bias[n+1]; }
                    if (T.C)
                        *(float2*)(T.C + (long)mm*T.ldC + n) = make_float2(v0, v1);
                    if (T.Chi) {
                        bf16 h0 = __float2bfloat16_rn(v0);
                        bf16 h1 = __float2bfloat16_rn(v1);
                        bf16 l0 = __float2bfloat16_rn(v0 - __bfloat162float(h0));
                        bf16 l1 = __float2bfloat16_rn(v1 - __bfloat162float(h1));
                        *(uint32_t*)(T.Chi + (long)mm*T.ldC + n) = pk2(h0, h1);
                        *(uint32_t*)(T.Clo + (long)mm*T.ldC + n) = pk2(l0, l1);
                        if (T.Cthi) {
                            T.Cthi[(long)n*T.ldCt + mm]       = h0;
                            T.Ctlo[(long)n*T.ldCt + mm]       = l0;
                            T.Cthi[(long)(n+1)*T.ldCt + mm]   = h1;
                            T.Ctlo[(long)(n+1)*T.ldCt + mm]   = l1;
                        }
                    }
                }
            }
        }
    }
}

// ========================= batched GEMM launch ==============================
__global__ void __launch_bounds__(256, 2)
gemm_mma(GTaskSet ts)
{
    extern __shared__ char smem[];
    int b = blockIdx.x, ti = 0;
    while (b >= ts.t[ti].blocks) { b -= ts.t[ti].blocks; ti++; }
    gemm_tile(ts.t[ti], b, smem);
}

// ========================= prep: split + transposes =========================
__global__ void prep_kernel(STaskSet ts, int split_blocks,
                            const float* __restrict__ A,
                            bf16* __restrict__ athi, bf16* __restrict__ atlo,
                            const float* __restrict__ B,
                            bf16* __restrict__ bthi, bf16* __restrict__ btlo)
{
    int b = blockIdx.x;
    if (b < split_blocks) {
        int ti = 0;
        while (b >= ts.t[ti].blocks) { b -= ts.t[ti].blocks; ti++; }
        const STask S = ts.t[ti];
        long idx = ((long)b * 256 + threadIdx.x) * 8;
        float4 u = *(const float4*)(S.src + idx);
        float4 v = *(const float4*)(S.src + idx + 4);
        uint4 hi, lo;
        split8(u, v, hi, lo);
        *(uint4*)(S.hi + idx) = hi;
        *(uint4*)(S.lo + idx) = lo;
        return;
    }
    int tb = b - split_blocks;
    int z  = tb >> 8;
    int rem = tb & 255;
    int bx = (rem & 15) * 32, by = (rem >> 4) * 32;
    int tx = threadIdx.x & 31, ty = threadIdx.x >> 5;
    __shared__ float t[32][33];
    const float* src = z ? B : A;
    bf16* dh = z ? bthi : athi;
    bf16* dl = z ? btlo : atlo;
    int x = bx + tx;
    #pragma unroll
    for (int i = 0; i < 32; i += 8) {
        int y = by + ty + i;
        t[ty + i][tx] = src[(long)y*DD + x];
    }
    __syncthreads();
    int xo = by + tx;
    #pragma unroll
    for (int i = 0; i < 32; i += 8) {
        int yo = bx + ty + i;
        float v = t[tx][ty + i];
        bf16 h = __float2bfloat16_rn(v);
        dh[(long)yo*DD + xo] = h;
        dl[(long)yo*DD + xo] = __float2bfloat16_rn(v - __bfloat162float(h));
    }
}

// ========================= S1 fused ==========================================
__device__ __forceinline__ float sigf(float x) { return 1.0f / (1.0f + expf(-x)); }

__global__ void s1_kernel(const float* __restrict__ h1,
                          const float* __restrict__ dn_g,
                          const float* __restrict__ dn_beta,
                          const float* __restrict__ w2,
                          const float* __restrict__ b2,
                          float* __restrict__ delta,
                          const float* __restrict__ proj_w,
                          const float* __restrict__ aob,
                          const float* __restrict__ proj_b,
                          float* __restrict__ pvec,
                          const float* __restrict__ gA,
                          const float* __restrict__ gB,
                          const float* __restrict__ bih,
                          const float* __restrict__ bhh,
                          const float* __restrict__ lstm_c,
                          const float* __restrict__ decays,
                          float* __restrict__ h_new,
                          float* __restrict__ c_new,
                          bf16* __restrict__ hnh,
                          bf16* __restrict__ hnl)
{
    int blk = blockIdx.x, t = threadIdx.x;
    if (blk < 256) {
        __shared__ float red[256];
        int row = blk;
        const float* r = h1 + (long)row * DD;
        float x0 = r[t], x1 = r[t + 256];
        red[t] = x0 + x1; __syncthreads();
        for (int o = 128; o > 0; o >>= 1) { if (t < o) red[t] += red[t+o]; __syncthreads(); }
        float mean = red[0] * (1.0f/DD);
        __syncthreads();
        float d0 = x0 - mean, d1 = x1 - mean;
        red[t] = d0*d0 + d1*d1; __syncthreads();
        for (int o = 128; o > 0; o >>= 1) { if (t < o) red[t] += red[t+o]; __syncthreads(); }
        float inv = rsqrtf(red[0] * (1.0f/DD) + 1e-5f);
        __syncthreads();
        float y0 = d0 * inv * dn_g[t]     + dn_beta[t];
        float y1 = d1 * inv * dn_g[t+256] + dn_beta[t+256];
        y0 = 0.5f * y0 * (1.0f + erff(y0 * 0.70710678118654752f));
        y1 = 0.5f * y1 * (1.0f + erff(y1 * 0.70710678118654752f));
        red[t] = y0*w2[t] + y1*w2[t+256]; __syncthreads();
        for (int o = 128; o > 0; o >>= 1) { if (t < o) red[t] += red[t+o]; __syncthreads(); }
        if (t == 0) {
            float z = red[0] + b2[0];
            delta[row] = (z > 20.0f) ? z : log1pf(expf(z));
        }
    } else if (blk < 768) {
        __shared__ float red[256];
        int row = blk - 256;
        const float* r = proj_w + (long)row * 2560 + 512;
        red[t] = r[t]*aob[t] + r[t+256]*aob[t+256];
        __syncthreads();
        for (int o = 128; o > 0; o >>= 1) { if (t < o) red[t] += red[t+o]; __syncthreads(); }
        if (t == 0) pvec[row] = proj_b[row] + red[0];
    } else {
        int idx = (blk - 768) * 256 + t;
        int s = idx / (BB*DD);
        int r = idx - s * (BB*DD);
        int b = r >> 9;
        int d = r & 511;
        long gbase = ((long)s * BB + b) * 2048;
        const float* a = gA + gbase;
        const float* h = gB + gbase;
        const float* bi = bih + s*2048;
        const float* bh = bhh + s*2048;
        float ip = a[d]      + h[d]      + bi[d]      + bh[d];
        float fp = a[512+d]  + h[512+d]  + bi[512+d]  + bh[512+d];
        float gp = a[1024+d] + h[1024+d] + bi[1024+d] + bh[1024+d];
        float op = a[1536+d] + h[1536+d] + bi[1536+d] + bh[1536+d];
        float i_g = sigf(ip);
        float f_g = sigf(fp);
        float g_g = tanhf(gp);
        float o_g = sigf(op);
        float c   = lstm_c[idx];
        float craw = f_g * c + i_g * g_g;
        float hn   = o_g * tanhf(craw);
        float dec  = decays[s];
        h_new[idx] = hn;
        c_new[idx] = dec * c + (1.0f - dec) * craw;
        bf16 hh = __float2bfloat16_rn(hn);
        hnh[idx] = hh;
        hnl[idx] = __float2bfloat16_rn(hn - __bfloat162float(hh));
    }
}

// ========================= persistent chain kernel ===========================
__global__ void __launch_bounds__(256, 2)
chain_kernel(const bf16* __restrict__ hph, const bf16* __restrict__ hpl,
             const bf16* __restrict__ wpowh, const bf16* __restrict__ wpowl,
             float* __restrict__ U,
             bf16* __restrict__ th, bf16* __restrict__ tl,
             const float* __restrict__ delta,
             const float* __restrict__ h_prev,
             const float* __restrict__ bx,
             float* __restrict__ out_hssm,
             bf16* __restrict__ hsh, bf16* __restrict__ hsl)
{
    extern __shared__ char smem[];
    const int tid = threadIdx.x;
    const long PU = (long)BB * 8 * DD;
    const long idx0 = ((long)blockIdx.x * 256 + tid) * 2;
    const int row = (int)(idx0 >> 9);
    const int col = (int)(idx0 & 511);
    const float dval = delta[row];

    float y[2];
    y[0] = h_prev[idx0];
    y[1] = h_prev[idx0 + 1];

    for (int iter = 0; iter < 2; iter++) {
        {
            int kz   = blockIdx.x >> 7;
            int tile = blockIdx.x & 127;
            GTask T = {};
            T.Xhi = iter ? th : hph;  T.Xlo = iter ? tl : hpl;  T.ldX = DD;
            T.Whi = wpowh;            T.Wlo = wpowl;            T.ldW = DD;
            T.C = U + (long)kz * PU;  T.ldC = 8*DD;
            T.K = 256; T.kofs = kz*256; T.nsplit = NOSPLIT; T.mtiles = 2;
            gemm_tile(T, tile, smem);
        }
        grid_barrier(&g_gen1, &g_cnt1, 256);

        const int k0 = iter * 8;
        const float* u0 = U + (long)row * 4096 + col;
        float c = 1.0f, tlast[2] = {0.0f, 0.0f};
        for (int j = 0; j < 8; j++) {
            c *= dval / (float)(k0 + j + 1);
            #pragma unroll
            for (int e = 0; e < 2; e++) {
                float u = u0[j*512 + e] + u0[PU + j*512 + e];
                float term = c * u;
                tlast[e] = term;
                y[e] += term;
            }
        }
        if (iter == 0) {
            #pragma unroll
            for (int e = 0; e < 2; e++) {
                bf16 h = __float2bfloat16_rn(tlast[e]);
                th[idx0 + e] = h;
                tl[idx0 + e] = __float2bfloat16_rn(tlast[e] - __bfloat162float(h));
            }
            grid_barrier(&g_gen1, &g_cnt1, 256);
        } else {
            #pragma unroll
            for (int e = 0; e < 2; e++) {
                float yy = y[e] + dval * bx[idx0 + e];
                out_hssm[idx0 + e] = yy;
                bf16 h = __float2bfloat16_rn(yy);
                hsh[idx0 + e] = h;
                hsl[idx0 + e] = __float2bfloat16_rn(yy - __bfloat162float(h));
            }
        }
    }
}

// ========================= persistent tail kernel ============================
// 256 blocks: [q sK4 (64) + hssm-proj sK4 (64) + hnew-proj sK2 (96)] ->
// barrier -> attn -> barrier -> [ctx@M sK4 (64)] -> barrier -> proj(14)+LN.
__global__ void __launch_bounds__(256, 2)
tail_kernel(const bf16* __restrict__ hsh, const bf16* __restrict__ hsl,
            const bf16* __restrict__ aiwh, const bf16* __restrict__ aiwl,
            const bf16* __restrict__ pwh, const bf16* __restrict__ pwl,
            const bf16* __restrict__ mh, const bf16* __restrict__ ml,
            const bf16* __restrict__ hnh, const bf16* __restrict__ hnl,
            float* __restrict__ qp, float* __restrict__ kvp,
            float* __restrict__ part,
            const float* __restrict__ attn_in_b,
            bf16* __restrict__ cxh, bf16* __restrict__ cxl,
            const float* __restrict__ pvec,
            const float* __restrict__ pg, const float* __restrict__ pbe,
            float* __restrict__ out_y)
{
    extern __shared__ char smem[];
    const int tid = threadIdx.x;
    const int blk = blockIdx.x;

    // ---- phase A ----
    if (blk < 224) {
        GTask T = {};
        T.nsplit = NOSPLIT; T.mtiles = 2;
        if (blk < 64) {                 // q split-K4
            int kz = blk >> 4;
            T.Xhi = hsh; T.Xlo = hsl; T.ldX = DD;
            T.Whi = aiwh; T.Wlo = aiwl; T.ldW = DD;
            T.C = qp + (long)kz*BB*DD; T.ldC = DD;
            T.K = 128; T.kofs = kz*128;
            gemm_tile(T, blk & 15, smem);
        } else if (blk < 128) {         // hssm proj split-K4
            int b2 = blk - 64;
            int kz = b2 >> 4;
            T.Xhi = hsh; T.Xlo = hsl; T.ldX = DD;
            T.Whi = pwh; T.Wlo = pwl; T.ldW = 5*DD;
            T.C = part + (long)kz*BB*DD; T.ldC = DD;
            T.K = 128; T.kofs = kz*128;
            gemm_tile(T, b2 & 15, smem);
        } else {                        // hnew proj split-K2 (3 states)
            int b3 = blk - 128;         // 0..95
            int i  = b3 >> 5;           // state 0..2
            int b2 = b3 & 31;
            int kz = b2 >> 4;
            T.Xhi = hnh + (long)i*BB*DD; T.Xlo = hnl + (long)i*BB*DD; T.ldX = DD;
            T.Whi = pwh + 1024 + i*512; T.Wlo = pwl + 1024 + i*512; T.ldW = 5*DD;
            T.C = part + (long)(8 + i*2 + kz)*BB*DD; T.ldC = DD;
            T.K = 256; T.kofs = kz*256;
            gemm_tile(T, b2 & 15, smem);
        }
    }
    grid_barrier(&g_gen2, &g_cnt2, 256);

    // ---- phase B: attention (block = batch) ----
    {
        int b    = blk;
        int warp = tid >> 5;
        int lane = tid & 31;
        const long QP = (long)BB*DD;
        const long KP = (long)SS*BB*2*DD;

        long qo = (long)b * DD + warp * 64;
        float q0 = attn_in_b[warp*64 + lane];
        float q1 = attn_in_b[warp*64 + lane + 32];
        #pragma unroll
        for (int p = 0; p < 4; p++) {
            q0 += qp[p*QP + qo + lane];
            q1 += qp[p*QP + qo + lane + 32];
        }

        float sc[SS];
        #pragma unroll
        for (int s = 0; s < SS; s++) {
            long ko = (long)(s*BB + b) * 1024 + warp * 64;
            float k0 = kvp[ko + lane]      + kvp[KP + ko + lane]
                     + attn_in_b[512 + warp*64 + lane];
            float k1 = kvp[ko + lane + 32] + kvp[KP + ko + lane + 32]
                     + attn_in_b[512 + warp*64 + lane + 32];
            float d = q0 * k0 + q1 * k1;
            #pragma unroll
            for (int o = 16; o > 0; o >>= 1) d += __shfl_xor_sync(0xffffffff, d, o);
            sc[s] = d * 0.125f;
        }
        float m = fmaxf(sc[0], fmaxf(sc[1], sc[2]));
        float e[SS], sum = 0.0f;
        #pragma unroll
        for (int s = 0; s < SS; s++) { e[s] = expf(sc[s] - m); sum += e[s]; }
        float inv = 1.0f / sum;

        float c0 = 0.0f, c1 = 0.0f;
        #pragma unroll
        for (int s = 0; s < SS; s++) {
            long vo = (long)(s*BB + b) * 1024 + 512 + warp * 64;
            float v0 = kvp[vo + lane]      + kvp[KP + vo + lane]
                     + attn_in_b[1024 + warp*64 + lane];
            float v1 = kvp[vo + lane + 32] + kvp[KP + vo + lane + 32]
                     + attn_in_b[1024 + warp*64 + lane + 32];
            float w = e[s] * inv;
            c0 += w * v0;
            c1 += w * v1;
        }
        long o0 = (long)b * DD + warp*64 + lane;
        bf16 h0 = __float2bfloat16_rn(c0);
        bf16 h1 = __float2bfloat16_rn(c1);
        cxh[o0]      = h0;
        cxl[o0]      = __float2bfloat16_rn(c0 - __bfloat162float(h0));
        cxh[o0 + 32] = h1;
        cxl[o0 + 32] = __float2bfloat16_rn(c1 - __bfloat162float(h1));
    }
    grid_barrier(&g_gen2, &g_cnt2, 256);

    // ---- phase C: ctx @ M split-K4 (64 blk) -> part planes 4..7 ----
    if (blk < 64) {
        int kz = blk >> 4;
        GTask T = {};
        T.Xhi = cxh; T.Xlo = cxl; T.ldX = DD;
        T.Whi = mh; T.Wlo = ml; T.ldW = DD;
        T.C = part + (long)(4+kz)*BB*DD; T.ldC = DD;
        T.K = 128; T.kofs = kz*128; T.nsplit = NOSPLIT; T.mtiles = 2;
        gemm_tile(T, blk & 15, smem);
    }
    grid_barrier(&g_gen2, &g_cnt2, 256);

    // ---- phase D: proj reduce (14 planes) + LN ----
    {
        float* red = (float*)smem;
        int row = blk, t = tid;
        long o0 = (long)row*DD + t, o1 = o0 + 256;
        const long PL = (long)BB*DD;
        float x0 = pvec[t], x1 = pvec[t+256];
        #pragma unroll
        for (int p = 0; p < 14; p++) { x0 += part[p*PL + o0]; x1 += part[p*PL + o1]; }

        red[t] = x0 + x1; __syncthreads();
        for (int o = 128; o > 0; o >>= 1) { if (t < o) red[t] += red[t+o]; __syncthreads(); }
        float mean = red[0] * (1.0f/DD);
        __syncthreads();

        float d0 = x0 - mean, d1 = x1 - mean;
        red[t] = d0*d0 + d1*d1; __syncthreads();
        for (int o = 128; o > 0; o >>= 1) { if (t < o) red[t] += red[t+o]; __syncthreads(); }
        float inv = rsqrtf(red[0] * (1.0f/DD) + 1e-5f);

        out_y[o0] = d0 * inv * pg[t]     + pbe[t];
        out_y[o1] = d1 * inv * pg[t+256] + pbe[t+256];
    }
}

// ---------------------------------------------------------------------------
static inline GTask mk_task(const bf16* Xhi, const bf16* Xlo, int ldX,
                            const bf16* Whi, const bf16* Wlo, int ldW,
                            float* C, int ldC, int K, int kofs,
                            int mtiles, int ntiles)
{
    GTask t = {};
    t.Xhi = Xhi; t.Xlo = Xlo; t.ldX = ldX;
    t.Whi = Whi; t.Wlo = Wlo; t.ldW = ldW;
    t.C = C; t.ldC = ldC;
    t.K = K; t.kofs = kofs; t.nsplit = NOSPLIT;
    t.mtiles = mtiles; t.blocks = mtiles*ntiles;
    return t;
}

extern "C" void kernel_launch(void* const* d_in, const int* in_sizes, int n_in,
                              void* d_out, int out_size)
{
    (void)in_sizes; (void)n_in; (void)out_size;

    const float* x        = (const float*)d_in[0];
    const float* h_prev   = (const float*)d_in[1];
    const float* lstm_h   = (const float*)d_in[2];
    const float* lstm_c   = (const float*)d_in[3];
    const float* A        = (const float*)d_in[4];
    const float* Bm       = (const float*)d_in[5];
    const float* dn_w1    = (const float*)d_in[6];
    const float* dn_b1    = (const float*)d_in[7];
    const float* dn_g     = (const float*)d_in[8];
    const float* dn_beta  = (const float*)d_in[9];
    const float* dn_w2    = (const float*)d_in[10];
    const float* dn_b2    = (const float*)d_in[11];
    const float* lstm_wih = (const float*)d_in[12];
    const float* lstm_whh = (const float*)d_in[13];
    const float* lstm_bih = (const float*)d_in[14];
    const float* lstm_bhh = (const float*)d_in[15];
    const float* decays   = (const float*)d_in[16];
    const float* attn_in_w  = (const float*)d_in[17];
    const float* attn_in_b  = (const float*)d_in[18];
    const float* attn_out_w = (const float*)d_in[19];
    const float* attn_out_b = (const float*)d_in[20];
    const float* proj_w   = (const float*)d_in[21];
    const float* proj_b   = (const float*)d_in[22];
    const float* proj_g   = (const float*)d_in[23];
    const float* proj_beta= (const float*)d_in[24];

    float* out = (float*)d_out;
    float* out_y    = out;
    float* out_hssm = out + BB*DD;
    float* out_hnew = out + 2*BB*DD;
    float* out_cnew = out + 2*BB*DD + SS*BB*DD;

    float *p_h1, *p_delta, *p_bx, *p_U, *p_gA, *p_gB, *p_kvp, *p_qp, *p_part, *p_pvec;
    cudaGetSymbolAddress((void**)&p_h1,    g_h1);
    cudaGetSymbolAddress((void**)&p_delta, g_delta);
    cudaGetSymbolAddress((void**)&p_bx,    g_bx);
    cudaGetSymbolAddress((void**)&p_U,     g_U);
    cudaGetSymbolAddress((void**)&p_gA,    g_gA);
    cudaGetSymbolAddress((void**)&p_gB,    g_gB);
    cudaGetSymbolAddress((void**)&p_kvp,   g_kvp);
    cudaGetSymbolAddress((void**)&p_qp,    g_qp);
    cudaGetSymbolAddress((void**)&p_part,  g_part);
    cudaGetSymbolAddress((void**)&p_pvec,  g_pvec);

    bf16 *xh,*xl,*hph,*hpl,*lhh,*lhl,*w1h,*w1l,*bmh,*bml,*wihh,*wihl,*whhh,*whhl,
         *aiwh,*aiwl,*pwh,*pwl,*wpowh,*wpowl,*ath,*atl,*a2th,*a2tl,*a4th,*a4tl,
         *aoth,*aotl,*mh,*ml,*th,*tl,*hsh,*hsl,*hnh,*hnl,*cxh,*cxl;
    cudaGetSymbolAddress((void**)&xh, g_xh);     cudaGetSymbolAddress((void**)&xl, g_xl);
    cudaGetSymbolAddress((void**)&hph, g_hph);   cudaGetSymbolAddress((void**)&hpl, g_hpl);
    cudaGetSymbolAddress((void**)&lhh, g_lhh);   cudaGetSymbolAddress((void**)&lhl, g_lhl);
    cudaGetSymbolAddress((void**)&w1h, g_w1h);   cudaGetSymbolAddress((void**)&w1l, g_w1l);
    cudaGetSymbolAddress((void**)&bmh, g_bmh);   cudaGetSymbolAddress((void**)&bml, g_bml);
    cudaGetSymbolAddress((void**)&wihh, g_wihh); cudaGetSymbolAddress((void**)&wihl, g_wihl);
    cudaGetSymbolAddress((void**)&whhh, g_whhh); cudaGetSymbolAddress((void**)&whhl, g_whhl);
    cudaGetSymbolAddress((void**)&aiwh, g_aiwh); cudaGetSymbolAddress((void**)&aiwl, g_aiwl);
    cudaGetSymbolAddress((void**)&pwh, g_pwh);   cudaGetSymbolAddress((void**)&pwl, g_pwl);
    cudaGetSymbolAddress((void**)&wpowh, g_wpowh); cudaGetSymbolAddress((void**)&wpowl, g_wpowl);
    cudaGetSymbolAddress((void**)&ath, g_ath);   cudaGetSymbolAddress((void**)&atl, g_atl);
    cudaGetSymbolAddress((void**)&a2th, g_a2th); cudaGetSymbolAddress((void**)&a2tl, g_a2tl);
    cudaGetSymbolAddress((void**)&a4th, g_a4th); cudaGetSymbolAddress((void**)&a4tl, g_a4tl);
    cudaGetSymbolAddress((void**)&aoth, g_aoth); cudaGetSymbolAddress((void**)&aotl, g_aotl);
    cudaGetSymbolAddress((void**)&mh, g_mh);     cudaGetSymbolAddress((void**)&ml, g_ml);
    cudaGetSymbolAddress((void**)&th, g_th);     cudaGetSymbolAddress((void**)&tl, g_tl);
    cudaGetSymbolAddress((void**)&hsh, g_hsh);   cudaGetSymbolAddress((void**)&hsl, g_hsl);
    cudaGetSymbolAddress((void**)&hnh, g_hnh);   cudaGetSymbolAddress((void**)&hnl, g_hnl);
    cudaGetSymbolAddress((void**)&cxh, g_cxh);   cudaGetSymbolAddress((void**)&cxl, g_cxl);

    cudaFuncSetAttribute(gemm_mma,
        cudaFuncAttributeMaxDynamicSharedMemorySize, SMEM_SZ);
    cudaFuncSetAttribute(chain_kernel,
        cudaFuncAttributeMaxDynamicSharedMemorySize, SMEM_SZ);
    cudaFuncSetAttribute(tail_kernel,
        cudaFuncAttributeMaxDynamicSharedMemorySize, SMEM_SZ);

    const long W2 = (long)DD*DD;
    const long KP = (long)SS*BB*2*DD;

    // ---- K1: split all operands + transposes ----
    {
        STaskSet st = {};
        auto add = [&](int i, const float* s, bf16* h, bf16* l, long n) {
            st.t[i] = { s, h, l, (int)(n / 2048) };
        };
        add(0, x,        xh,   xl,   (long)BB*DD);
        add(1, h_prev,   hph,  hpl,  (long)BB*DD);
        add(2, lstm_h,   lhh,  lhl,  (long)SS*BB*DD);
        add(3, dn_w1,    w1h,  w1l,  W2);
        add(4, Bm,       bmh,  bml,  W2);
        add(5, lstm_wih, wihh, wihl, (long)SS*4*W2);
        add(6, lstm_whh, whhh, whhl, (long)SS*4*W2);
        add(7, attn_in_w, aiwh, aiwl, 3*W2);
        add(8, proj_w,   pwh,  pwl,  5*W2);
        add(9, A,        wpowh, wpowl, W2);
        st.ntasks = 10;
        int total = 0;
        for (int i = 0; i < 10; i++) total += st.t[i].blocks;
        prep_kernel<<<total + 512, 256>>>(st, total,
            A, ath, atl, attn_out_w, aoth, aotl);
    }

    // ---- K2 (G1, 480 blocks): h1|bx, 6 lstm partials, A^2 (+A2T), M ----
    {
        GTaskSet ts = {};
        GTask t0 = mk_task(xh, xl, DD, w1h, w1l, DD, p_h1, DD, DD, 0, 2, 16);
        t0.bias = dn_b1; t0.Wn2hi = bmh; t0.Wn2lo = bml;
        t0.Cn2 = p_bx; t0.ldCn2 = DD; t0.nsplit = DD;
        ts.t[0] = t0;
        for (int s = 0; s < SS; s++) {
            ts.t[1+s] = mk_task(xh, xl, DD, wihh + (long)s*4*W2, wihl + (long)s*4*W2, DD,
                                p_gA + (long)s*BB*4*DD, 4*DD, DD, 0, 2, 32);
            ts.t[4+s] = mk_task(lhh + (long)s*BB*DD, lhl + (long)s*BB*DD, DD,
                                whhh + (long)s*4*W2, whhl + (long)s*4*W2, DD,
                                p_gB + (long)s*BB*4*DD, 4*DD, DD, 0, 2, 32);
        }
        GTask ta = mk_task(wpowh, wpowl, DD, ath, atl, DD, nullptr, DD, DD, 0, 4, 8);
        ta.Chi = wpowh + W2; ta.Clo = wpowl + W2;
        ta.Cthi = a2th; ta.Ctlo = a2tl; ta.ldCt = DD;
        ts.t[7] = ta;
        GTask tm = mk_task(pwh + 512, pwl + 512, 5*DD, aoth, aotl, DD,
                           nullptr, DD, DD, 0, 4, 8);
        tm.Chi = mh; tm.Clo = ml;
        ts.t[8] = tm;
        ts.ntasks = 9;
        gemm_mma<<<480, 256, SMEM_SZ>>>(ts);
    }

    // ---- K3: S1 fused ----
    s1_kernel<<<2304, 256>>>(p_h1, dn_g, dn_beta, dn_w2, dn_b2, p_delta,
                             proj_w, attn_out_b, proj_b, p_pvec,
                             p_gA, p_gB, lstm_bih, lstm_bhh, lstm_c, decays,
                             out_hnew, out_cnew, hnh, hnl);

    // ---- K4 (G2, 256 blocks): A^3, A^4 (+A4T), kv split-K-2 ----
    {
        GTaskSet ts = {};
        GTask t3 = mk_task(wpowh + W2, wpowl + W2, DD, ath, atl, DD,
                           nullptr, DD, DD, 0, 4, 8);
        t3.Chi = wpowh + 2*W2; t3.Clo = wpowl + 2*W2;
        ts.t[0] = t3;
        GTask t4 = mk_task(wpowh + W2, wpowl + W2, DD, a2th, a2tl, DD,
                           nullptr, DD, DD, 0, 4, 8);
        t4.Chi = wpowh + 3*W2; t4.Clo = wpowl + 3*W2;
        t4.Cthi = a4th; t4.Ctlo = a4tl; t4.ldCt = DD;
        ts.t[1] = t4;
        for (int kz = 0; kz < 2; kz++)
            ts.t[2+kz] = mk_task(hnh, hnl, DD, aiwh + W2, aiwl + W2, DD,
                                 p_kvp + (long)kz*KP, 2*DD, 256, kz*256, 6, 16);
        ts.ntasks = 4;
        gemm_mma<<<256, 256, SMEM_SZ>>>(ts);
    }

    // ---- K5 (128 blocks, uniform K=512): A^5..A^8 ----
    {
        GTaskSet ts = {};
        GTask t5 = mk_task(wpowh + 3*W2, wpowl + 3*W2, DD, ath, atl, DD,
                           nullptr, DD, DD, 0, 4, 8);
        t5.Chi = wpowh + 4*W2; t5.Clo = wpowl + 4*W2;
        ts.t[0] = t5;
        GTask t6 = mk_task(wpowh + 3*W2, wpowl + 3*W2, DD, a2th, a2tl, DD,
                           nullptr, DD, DD, 0, 4, 8);
        t6.Chi = wpowh + 5*W2; t6.Clo = wpowl + 5*W2;
        ts.t[1] = t6;
        GTask t7 = mk_task(wpowh + 2*W2, wpowl + 2*W2, DD, a4th, a4tl, DD,
                           nullptr, DD, DD, 0, 4, 8);
        t7.Chi = wpowh + 6*W2; t7.Clo = wpowl + 6*W2;
        ts.t[2] = t7;
        GTask t8 = mk_task(wpowh + 3*W2, wpowl + 3*W2, DD, a4th, a4tl, DD,
                           nullptr, DD, DD, 0, 4, 8);
        t8.Chi = wpowh + 7*W2; t8.Clo = wpowl + 7*W2;
        ts.t[3] = t8;
        ts.ntasks = 4;
        gemm_mma<<<128, 256, SMEM_SZ>>>(ts);
    }

    // ---- K6: persistent chain (split-K-2, 256 blocks) ----
    chain_kernel<<<256, 256, SMEM_SZ>>>(hph, hpl, wpowh, wpowl, p_U, th, tl,
                                        p_delta, h_prev, p_bx,
                                        out_hssm, hsh, hsl);

    // ---- K7: persistent tail ----
    tail_kernel<<<256, 256, SMEM_SZ>>>(hsh, hsl, aiwh, aiwl, pwh, pwl, mh, ml,
                                       hnh, hnl,
                                       p_qp, p_kvp, p_part, attn_in_b,
                                       cxh, cxl, p_pvec, proj_g, proj_beta,
                                       out_y);
}

// round 16
// speedup vs baseline: 1.1176x; 1.0351x over previous
#include <cuda_runtime.h>
#include <cuda_bf16.h>
#include <cuda_fp16.h>
#include <math.h>
#include <cstdint>

// ---------------------------------------------------------------------------
// SSMXLSTMFusion: D=512, S=3, BATCH=256, H=8, HD=64
// Round 16: R12 task graph (best) + 1 sync/chunk + fp16 2-product mode for
// non-compounding GEMMs (LSTM gates, M, hssm/hnew-proj, ctx@M): 1/3 fewer
// mma on 42% of the work. Error-amplifying paths (delta/h1, chain, A-powers,
// q/kv) stay bf16 3-product. Chain 2x8 terms (A^1..A^8, KT=16).
// ---------------------------------------------------------------------------

#define DD    512
#define BB    256
#define SS    3
typedef __nv_bfloat16 bf16;

// ------------------------- fp32 scratch ------------------------------------
__device__ float g_h1   [BB*DD];
__device__ float g_delta[BB];
__device__ float g_bx   [BB*DD];
__device__ float g_U    [2*BB*8*DD];
__device__ float g_gA   [SS*BB*4*DD];
__device__ float g_gB   [SS*BB*4*DD];
__device__ float g_kvp  [2*SS*BB*2*DD];
__device__ float g_qp   [4*BB*DD];
__device__ float g_part [14*BB*DD];           // hssm 0-3, ctx 4-7, hnew 8-13
__device__ float g_pvec [DD];

// ------------------------- bf16 hi/lo planes (3-product path) ---------------
__device__ bf16 g_xh[BB*DD],          g_xl[BB*DD];
__device__ bf16 g_hph[BB*DD],         g_hpl[BB*DD];
__device__ bf16 g_w1h[DD*DD],         g_w1l[DD*DD];
__device__ bf16 g_bmh[DD*DD],         g_bml[DD*DD];
__device__ bf16 g_aiwh[3*DD*DD],      g_aiwl[3*DD*DD];
__device__ bf16 g_wpowh[8*DD*DD],     g_wpowl[8*DD*DD];
__device__ bf16 g_ath[DD*DD],         g_atl[DD*DD];
__device__ bf16 g_a2th[DD*DD],        g_a2tl[DD*DD];
__device__ bf16 g_a4th[DD*DD],        g_a4tl[DD*DD];
__device__ bf16 g_th[BB*DD],          g_tl[BB*DD];
__device__ bf16 g_hsh[BB*DD],         g_hsl[BB*DD];
__device__ bf16 g_hnh[SS*BB*DD],      g_hnl[SS*BB*DD];

// ------------------------- fp16 hi/lo planes (2-product path, bit-stored) ---
__device__ bf16 g_x16h[BB*DD],        g_x16l[BB*DD];
__device__ bf16 g_lh16h[SS*BB*DD],    g_lh16l[SS*BB*DD];
__device__ bf16 g_wih16h[SS*4*DD*DD], g_wih16l[SS*4*DD*DD];
__device__ bf16 g_whh16h[SS*4*DD*DD], g_whh16l[SS*4*DD*DD];
__device__ bf16 g_pw16h[DD*5*DD],     g_pw16l[DD*5*DD];
__device__ bf16 g_aot16h[DD*DD],      g_aot16l[DD*DD];
__device__ bf16 g_m16h[DD*DD],        g_m16l[DD*DD];
__device__ bf16 g_hs16h[BB*DD],       g_hs16l[BB*DD];
__device__ bf16 g_hn16h[SS*BB*DD],    g_hn16l[SS*BB*DD];
__device__ bf16 g_cx16h[BB*DD],       g_cx16l[BB*DD];

__device__ volatile unsigned g_gen1; __device__ unsigned g_cnt1;
__device__ volatile unsigned g_gen2; __device__ unsigned g_cnt2;

// ========================= descriptors ======================================
struct GTask {
    const bf16 *Xhi, *Xlo, *Whi, *Wlo, *Wn2hi, *Wn2lo;
    const float* bias;
    float *C, *Cn2;
    bf16 *Chi, *Clo, *Cthi, *Ctlo;
    int ldX, ldW, ldC, ldCn2, ldCt;
    int K, kofs, nsplit, mtiles, blocks, fp2;
};
struct GTaskSet { GTask t[12]; int ntasks; };

struct STask { const float* src; bf16 *hi, *lo; int blocks; int half; };
struct STaskSet { STask t[12]; int ntasks; };

#define NOSPLIT (1<<30)

// ========================= smem layout ======================================
#define RSB     80
#define OFF_AHI 0
#define OFF_ALO 10240
#define OFF_BHI 20480
#define OFF_BLO 25600
#define STAGE   30720
#define SMEM_SZ (3*STAGE)      // 92160 bytes

__device__ __forceinline__ uint32_t smem_to_u32(const void* p) {
    uint32_t a;
    asm("{ .reg .u64 t; cvta.to.shared.u64 t, %1; cvt.u32.u64 %0, t; }"
        : "=r"(a) : "l"(p));
    return a;
}

__device__ __forceinline__ uint32_t pk2(bf16 a, bf16 b) {
    uint16_t ua = *(uint16_t*)&a, ub = *(uint16_t*)&b;
    return (uint32_t)ua | ((uint32_t)ub << 16);
}
__device__ __forceinline__ uint32_t pk2h(__half a, __half b) {
    uint16_t ua = *(uint16_t*)&a, ub = *(uint16_t*)&b;
    return (uint32_t)ua | ((uint32_t)ub << 16);
}

__device__ __forceinline__ void split8(float4 u, float4 v, uint4& hi, uint4& lo)
{
    float f[8] = {u.x,u.y,u.z,u.w,v.x,v.y,v.z,v.w};
    uint32_t h[4], l[4];
    #pragma unroll
    for (int i = 0; i < 4; i++) {
        bf16 b0 = __float2bfloat16_rn(f[2*i]);
        bf16 b1 = __float2bfloat16_rn(f[2*i+1]);
        bf16 r0 = __float2bfloat16_rn(f[2*i]   - __bfloat162float(b0));
        bf16 r1 = __float2bfloat16_rn(f[2*i+1] - __bfloat162float(b1));
        h[i] = pk2(b0, b1);
        l[i] = pk2(r0, r1);
    }
    hi = make_uint4(h[0], h[1], h[2], h[3]);
    lo = make_uint4(l[0], l[1], l[2], l[3]);
}

__device__ __forceinline__ void split8h(float4 u, float4 v, uint4& hi, uint4& lo)
{
    float f[8] = {u.x,u.y,u.z,u.w,v.x,v.y,v.z,v.w};
    uint32_t h[4], l[4];
    #pragma unroll
    for (int i = 0; i < 4; i++) {
        __half b0 = __float2half_rn(f[2*i]);
        __half b1 = __float2half_rn(f[2*i+1]);
        __half r0 = __float2half_rn(f[2*i]   - __half2float(b0));
        __half r1 = __float2half_rn(f[2*i+1] - __half2float(b1));
        h[i] = pk2h(b0, b1);
        l[i] = pk2h(r0, r1);
    }
    hi = make_uint4(h[0], h[1], h[2], h[3]);
    lo = make_uint4(l[0], l[1], l[2], l[3]);
}

__device__ __forceinline__ void ldm_x4(uint32_t* r, uint32_t addr) {
    asm volatile("ldmatrix.sync.aligned.m8n8.x4.shared.b16 {%0,%1,%2,%3}, [%4];"
        : "=r"(r[0]), "=r"(r[1]), "=r"(r[2]), "=r"(r[3]) : "r"(addr));
}

__device__ __forceinline__ void mma_bf16(float* c, const uint32_t* a, const uint32_t* b)
{
    asm volatile(
        "mma.sync.aligned.m16n8k16.row.col.f32.bf16.bf16.f32 "
        "{%0,%1,%2,%3}, {%4,%5,%6,%7}, {%8,%9}, {%0,%1,%2,%3};"
        : "+f"(c[0]), "+f"(c[1]), "+f"(c[2]), "+f"(c[3])
        : "r"(a[0]), "r"(a[1]), "r"(a[2]), "r"(a[3]), "r"(b[0]), "r"(b[1]));
}

__device__ __forceinline__ void mma_f16(float* c, const uint32_t* a, const uint32_t* b)
{
    asm volatile(
        "mma.sync.aligned.m16n8k16.row.col.f32.f16.f16.f32 "
        "{%0,%1,%2,%3}, {%4,%5,%6,%7}, {%8,%9}, {%0,%1,%2,%3};"
        : "+f"(c[0]), "+f"(c[1]), "+f"(c[2]), "+f"(c[3])
        : "r"(a[0]), "r"(a[1]), "r"(a[2]), "r"(a[3]), "r"(b[0]), "r"(b[1]));
}

#define CP16(saddr, gaddr) \
    asm volatile("cp.async.cg.shared.global [%0], [%1], 16;" \
        :: "r"(saddr), "l"(gaddr) : "memory")

__device__ __forceinline__ void grid_barrier(volatile unsigned* gen,
                                             unsigned* cnt, unsigned total)
{
    __syncthreads();
    if (threadIdx.x == 0) {
        unsigned mygen = *gen;
        __threadfence();
        unsigned t = atomicAdd(cnt, 1u);
        if (t == total - 1) {
            *cnt = 0;
            __threadfence();
            *gen = mygen + 1;
        } else {
            while (*gen == mygen) { __nanosleep(32); }
            __threadfence();
        }
    }
    __syncthreads();
}

// ------------------------- GEMM tile (device) --------------------------------
__device__ __forceinline__ void issue_chunk(const GTask& T, uint32_t smb,
    int m0, int n0, int tid, int k0, int stage)
{
    const uint32_t sb = smb + (uint32_t)(stage * STAGE);
    #pragma unroll
    for (int j = 0; j < 4; j++) {
        int o  = tid + j*256;
        int pl = o >> 9;
        int r  = (o >> 2) & 127;
        int s  = o & 3;
        const bf16* g = (pl ? T.Xlo : T.Xhi) + (long)(m0 + r) * T.ldX + k0 + s*8;
        uint32_t sa = sb + (uint32_t)(pl*10240 + r*80 + s*16);
        CP16(sa, g);
    }
    #pragma unroll
    for (int j = 0; j < 2; j++) {
        int o  = tid + j*256;
        int pl = o >> 8;
        int r  = (o >> 2) & 63;
        int s  = o & 3;
        int ng = n0 + r;
        const bf16* w;
        if (ng >= T.nsplit)
            w = (pl ? T.Wn2lo : T.Wn2hi) + (long)(ng - T.nsplit) * T.ldW;
        else
            w = (pl ? T.Wlo : T.Whi) + (long)ng * T.ldW;
        uint32_t sa = sb + (uint32_t)(20480 + pl*5120 + r*80 + s*16);
        CP16(sa, w + k0 + s*8);
    }
    asm volatile("cp.async.commit_group;" ::: "memory");
}

__device__ void gemm_tile(const GTask& T, int b, char* smem)
{
    const int m0 = (b % T.mtiles) * 128;
    const int n0 = (b / T.mtiles) * 64;

    const int tid = threadIdx.x;
    const int lid = tid & 31;
    const int wid = tid >> 5;
    const int m_base = (wid & 3) * 32;
    const int n_base = (wid >> 2) * 32;
    const int gid = lid >> 2;
    const int tig = lid & 3;
    const int g  = lid >> 3;
    const int ig = lid & 7;

    const uint32_t smb = smem_to_u32(smem);
    const uint32_t a_ad = smb + (uint32_t)((m_base + (g&1)*8 + ig) * RSB + (g>>1)*16);
    const uint32_t b_ad = smb + (uint32_t)((n_base + (g>>1)*8 + ig) * RSB + (g&1)*16);

    float acc[2][4][4];
    #pragma unroll
    for (int i = 0; i < 2; i++)
        #pragma unroll
        for (int j = 0; j < 4; j++)
            #pragma unroll
            for (int k = 0; k < 4; k++) acc[i][j][k] = 0.0f;

    const int nc = T.K >> 5;

    issue_chunk(T, smb, m0, n0, tid, T.kofs, 0);
    if (nc > 1) issue_chunk(T, smb, m0, n0, tid, T.kofs + 32, 1);

    for (int c = 0; c < nc; c++) {
        if (c + 1 < nc)
            asm volatile("cp.async.wait_group 1;" ::: "memory");
        else
            asm volatile("cp.async.wait_group 0;" ::: "memory");
        __syncthreads();

        if (c + 2 < nc)
            issue_chunk(T, smb, m0, n0, tid, T.kofs + (c+2)*32, (c+2)%3);

        const uint32_t sb = (uint32_t)((c % 3) * STAGE);
        if (T.fp2) {
            // fp16 2-product: ahi*bhi + alo*bhi (B-lo unused)
            #pragma unroll
            for (int ks = 0; ks < 2; ks++) {
                const uint32_t kb = sb + ks * 32;
                uint32_t ahi[2][4], alo[2][4], bhi[4][2];
                #pragma unroll
                for (int mt = 0; mt < 2; mt++) {
                    ldm_x4(ahi[mt], a_ad + OFF_AHI + mt*16*RSB + kb);
                    ldm_x4(alo[mt], a_ad + OFF_ALO + mt*16*RSB + kb);
                }
                #pragma unroll
                for (int np = 0; np < 2; np++) {
                    uint32_t r[4];
                    ldm_x4(r, b_ad + OFF_BHI + np*16*RSB + kb);
                    bhi[2*np][0] = r[0]; bhi[2*np][1] = r[1];
                    bhi[2*np+1][0] = r[2]; bhi[2*np+1][1] = r[3];
                }
                #pragma unroll
                for (int mt = 0; mt < 2; mt++)
                    #pragma unroll
                    for (int nt = 0; nt < 4; nt++) {
                        mma_f16(acc[mt][nt], ahi[mt], bhi[nt]);
                        mma_f16(acc[mt][nt], alo[mt], bhi[nt]);
                    }
            }
        } else {
            #pragma unroll
            for (int ks = 0; ks < 2; ks++) {
                const uint32_t kb = sb + ks * 32;
                uint32_t ahi[2][4], alo[2][4], bhi[4][2], blo[4][2];
                #pragma unroll
                for (int mt = 0; mt < 2; mt++) {
                    ldm_x4(ahi[mt], a_ad + OFF_AHI + mt*16*RSB + kb);
                    ldm_x4(alo[mt], a_ad + OFF_ALO + mt*16*RSB + kb);
                }
                #pragma unroll
                for (int np = 0; np < 2; np++) {
                    uint32_t r[4];
                    ldm_x4(r, b_ad + OFF_BHI + np*16*RSB + kb);
                    bhi[2*np][0] = r[0]; bhi[2*np][1] = r[1];
                    bhi[2*np+1][0] = r[2]; bhi[2*np+1][1] = r[3];
                    ldm_x4(r, b_ad + OFF_BLO + np*16*RSB + kb);
                    blo[2*np][0] = r[0]; blo[2*np][1] = r[1];
                    blo[2*np+1][0] = r[2]; blo[2*np+1][1] = r[3];
                }
                #pragma unroll
                for (int mt = 0; mt < 2; mt++)
                    #pragma unroll
                    for (int nt = 0; nt < 4; nt++) {
                        mma_bf16(acc[mt][nt], ahi[mt], bhi[nt]);
                        mma_bf16(acc[mt][nt], ahi[mt], blo[nt]);
                        mma_bf16(acc[mt][nt], alo[mt], bhi[nt]);
                    }
            }
        }
        // single sync per chunk (top-of-loop sync covers the 3-stage ring)
    }

    #pragma unroll
    for (int mt = 0; mt < 2; mt++) {
        #pragma unroll
        for (int nt = 0; nt < 4; nt++) {
            int n = n0 + n_base + nt*8 + tig*2;
            #pragma unroll
            for (int half = 0; half < 2; half++) {
                int mm = m0 + m_base + mt*16 + gid + half*8;
                float v0 = acc[mt][nt][half*2];
                float v1 = acc[mt][nt][half*2 + 1];
                if (T.Cn2 && n >= T.nsplit) {
                    int nn = n - T.nsplit;
                    *(float2*)(T.Cn2 + (long)mm*T.ldCn2 + nn) = make_float2(v0, v1);
                } else {
                    if (T.bias) { v0 += T.bias[n]; v1 += T.bias[n+1]; }
                    if (T.C)
                        *(float2*)(T.C + (long)mm*T.ldC + n) = make_float2(v0, v1);
                    if (T.Chi) {
                        if (T.fp2) {
                            __half h0 = __float2half_rn(v0);
                            __half h1 = __float2half_rn(v1);
                            __half l0 = __float2half_rn(v0 - __half2float(h0));
                            __half l1 = __float2half_rn(v1 - __half2float(h1));
                            *(uint32_t*)(T.Chi + (long)mm*T.ldC + n) = pk2h(h0, h1);
                            *(uint32_t*)(T.Clo + (long)mm*T.ldC + n) = pk2h(l0, l1);
                        } else {
                            bf16 h0 = __float2bfloat16_rn(v0);
                            bf16 h1 = __float2bfloat16_rn(v1);
                            bf16 l0 = __float2bfloat16_rn(v0 - __bfloat162float(h0));
                            bf16 l1 = __float2bfloat16_rn(v1 - __bfloat162float(h1));
                            *(uint32_t*)(T.Chi + (long)mm*T.ldC + n) = pk2(h0, h1);
                            *(uint32_t*)(T.Clo + (long)mm*T.ldC + n) = pk2(l0, l1);
                            if (T.Cthi) {
                                T.Cthi[(long)n*T.ldCt + mm]       = h0;
                                T.Ctlo[(long)n*T.ldCt + mm]       = l0;
                                T.Cthi[(long)(n+1)*T.ldCt + mm]   = h1;
                                T.Ctlo[(long)(n+1)*T.ldCt + mm]   = l1;
                            }
                        }
                    }
                }
            }
        }
    }
}

// ========================= batched GEMM launch ==============================
__global__ void __launch_bounds__(256, 2)
gemm_mma(GTaskSet ts)
{
    extern __shared__ char smem[];
    int b = blockIdx.x, ti = 0;
    while (b >= ts.t[ti].blocks) { b -= ts.t[ti].blocks; ti++; }
    gemm_tile(ts.t[ti], b, smem);
}

// ========================= prep: split + transposes =========================
__global__ void prep_kernel(STaskSet ts, int split_blocks,
                            const float* __restrict__ A,
                            bf16* __restrict__ athi, bf16* __restrict__ atlo,
                            const float* __restrict__ B,
                            bf16* __restrict__ bthi, bf16* __restrict__ btlo)
{
    int b = blockIdx.x;
    if (b < split_blocks) {
        int ti = 0;
        while (b >= ts.t[ti].blocks) { b -= ts.t[ti].blocks; ti++; }
        const STask S = ts.t[ti];
        long idx = ((long)b * 256 + threadIdx.x) * 8;
        float4 u = *(const float4*)(S.src + idx);
        float4 v = *(const float4*)(S.src + idx + 4);
        uint4 hi, lo;
        if (S.half) split8h(u, v, hi, lo);
        else        split8(u, v, hi, lo);
        *(uint4*)(S.hi + idx) = hi;
        *(uint4*)(S.lo + idx) = lo;
        return;
    }
    int tb = b - split_blocks;
    int z  = tb >> 8;
    int rem = tb & 255;
    int bx = (rem & 15) * 32, by = (rem >> 4) * 32;
    int tx = threadIdx.x & 31, ty = threadIdx.x >> 5;
    __shared__ float t[32][33];
    const float* src = z ? B : A;
    bf16* dh = z ? bthi : athi;
    bf16* dl = z ? btlo : atlo;
    int x = bx + tx;
    #pragma unroll
    for (int i = 0; i < 32; i += 8) {
        int y = by + ty + i;
        t[ty + i][tx] = src[(long)y*DD + x];
    }
    __syncthreads();
    int xo = by + tx;
    #pragma unroll
    for (int i = 0; i < 32; i += 8) {
        int yo = bx + ty + i;
        float v = t[tx][ty + i];
        if (z) {  // attn_out_w^T -> fp16
            __half h = __float2half_rn(v);
            uint16_t uh = *(uint16_t*)&h;
            __half l = __float2half_rn(v - __half2float(h));
            uint16_t ul = *(uint16_t*)&l;
            *(uint16_t*)&dh[(long)yo*DD + xo] = uh;
            *(uint16_t*)&dl[(long)yo*DD + xo] = ul;
        } else {  // A^T -> bf16
            bf16 h = __float2bfloat16_rn(v);
            dh[(long)yo*DD + xo] = h;
            dl[(long)yo*DD + xo] = __float2bfloat16_rn(v - __bfloat162float(h));
        }
    }
}

// ========================= S1 fused ==========================================
__device__ __forceinline__ float sigf(float x) { return 1.0f / (1.0f + expf(-x)); }

__global__ void s1_kernel(const float* __restrict__ h1,
                          const float* __restrict__ dn_g,
                          const float* __restrict__ dn_beta,
                          const float* __restrict__ w2,
                          const float* __restrict__ b2,
                          float* __restrict__ delta,
                          const float* __restrict__ proj_w,
                          const float* __restrict__ aob,
                          const float* __restrict__ proj_b,
                          float* __restrict__ pvec,
                          const float* __restrict__ gA,
                          const float* __restrict__ gB,
                          const float* __restrict__ bih,
                          const float* __restrict__ bhh,
                          const float* __restrict__ lstm_c,
                          const float* __restrict__ decays,
                          float* __restrict__ h_new,
                          float* __restrict__ c_new,
                          bf16* __restrict__ hnh,
                          bf16* __restrict__ hnl,
                          bf16* __restrict__ hn16h,
                          bf16* __restrict__ hn16l)
{
    int blk = blockIdx.x, t = threadIdx.x;
    if (blk < 256) {
        __shared__ float red[256];
        int row = blk;
        const float* r = h1 + (long)row * DD;
        float x0 = r[t], x1 = r[t + 256];
        red[t] = x0 + x1; __syncthreads();
        for (int o = 128; o > 0; o >>= 1) { if (t < o) red[t] += red[t+o]; __syncthreads(); }
        float mean = red[0] * (1.0f/DD);
        __syncthreads();
        float d0 = x0 - mean, d1 = x1 - mean;
        red[t] = d0*d0 + d1*d1; __syncthreads();
        for (int o = 128; o > 0; o >>= 1) { if (t < o) red[t] += red[t+o]; __syncthreads(); }
        float inv = rsqrtf(red[0] * (1.0f/DD) + 1e-5f);
        __syncthreads();
        float y0 = d0 * inv * dn_g[t]     + dn_beta[t];
        float y1 = d1 * inv * dn_g[t+256] + dn_beta[t+256];
        y0 = 0.5f * y0 * (1.0f + erff(y0 * 0.70710678118654752f));
        y1 = 0.5f * y1 * (1.0f + erff(y1 * 0.70710678118654752f));
        red[t] = y0*w2[t] + y1*w2[t+256]; __syncthreads();
        for (int o = 128; o > 0; o >>= 1) { if (t < o) red[t] += red[t+o]; __syncthreads(); }
        if (t == 0) {
            float z = red[0] + b2[0];
            delta[row] = (z > 20.0f) ? z : log1pf(expf(z));
        }
    } else if (blk < 768) {
        __shared__ float red[256];
        int row = blk - 256;
        const float* r = proj_w + (long)row * 2560 + 512;
        red[t] = r[t]*aob[t] + r[t+256]*aob[t+256];
        __syncthreads();
        for (int o = 128; o > 0; o >>= 1) { if (t < o) red[t] += red[t+o]; __syncthreads(); }
        if (t == 0) pvec[row] = proj_b[row] + red[0];
    } else {
        int idx = (blk - 768) * 256 + t;
        int s = idx / (BB*DD);
        int r = idx - s * (BB*DD);
        int b = r >> 9;
        int d = r & 511;
        long gbase = ((long)s * BB + b) * 2048;
        const float* a = gA + gbase;
        const float* h = gB + gbase;
        const float* bi = bih + s*2048;
        const float* bh = bhh + s*2048;
        float ip = a[d]      + h[d]      + bi[d]      + bh[d];
        float fp = a[512+d]  + h[512+d]  + bi[512+d]  + bh[512+d];
        float gp = a[1024+d] + h[1024+d] + bi[1024+d] + bh[1024+d];
        float op = a[1536+d] + h[1536+d] + bi[1536+d] + bh[1536+d];
        float i_g = sigf(ip);
        float f_g = sigf(fp);
        float g_g = tanhf(gp);
        float o_g = sigf(op);
        float c   = lstm_c[idx];
        float craw = f_g * c + i_g * g_g;
        float hn   = o_g * tanhf(craw);
        float dec  = decays[s];
        h_new[idx] = hn;
        c_new[idx] = dec * c + (1.0f - dec) * craw;
        bf16 hh = __float2bfloat16_rn(hn);
        hnh[idx] = hh;
        hnl[idx] = __float2bfloat16_rn(hn - __bfloat162float(hh));
        __half hx = __float2half_rn(hn);
        __half lx = __float2half_rn(hn - __half2float(hx));
        *(uint16_t*)&hn16h[idx] = *(uint16_t*)&hx;
        *(uint16_t*)&hn16l[idx] = *(uint16_t*)&lx;
    }
}

// ========================= persistent chain kernel ===========================
__global__ void __launch_bounds__(256, 2)
chain_kernel(const bf16* __restrict__ hph, const bf16* __restrict__ hpl,
             const bf16* __restrict__ wpowh, const bf16* __restrict__ wpowl,
             float* __restrict__ U,
             bf16* __restrict__ th, bf16* __restrict__ tl,
             const float* __restrict__ delta,
             const float* __restrict__ h_prev,
             const float* __restrict__ bx,
             float* __restrict__ out_hssm,
             bf16* __restrict__ hsh, bf16* __restrict__ hsl,
             bf16* __restrict__ hs16h, bf16* __restrict__ hs16l)
{
    extern __shared__ char smem[];
    const int tid = threadIdx.x;
    const long PU = (long)BB * 8 * DD;
    const long idx0 = ((long)blockIdx.x * 256 + tid) * 2;
    const int row = (int)(idx0 >> 9);
    const int col = (int)(idx0 & 511);
    const float dval = delta[row];

    float y[2];
    y[0] = h_prev[idx0];
    y[1] = h_prev[idx0 + 1];

    for (int iter = 0; iter < 2; iter++) {
        {
            int kz   = blockIdx.x >> 7;
            int tile = blockIdx.x & 127;
            GTask T = {};
            T.Xhi = iter ? th : hph;  T.Xlo = iter ? tl : hpl;  T.ldX = DD;
            T.Whi = wpowh;            T.Wlo = wpowl;            T.ldW = DD;
            T.C = U + (long)kz * PU;  T.ldC = 8*DD;
            T.K = 256; T.kofs = kz*256; T.nsplit = NOSPLIT; T.mtiles = 2;
            gemm_tile(T, tile, smem);
        }
        grid_barrier(&g_gen1, &g_cnt1, 256);

        const int k0 = iter * 8;
        const float* u0 = U + (long)row * 4096 + col;
        float c = 1.0f, tlast[2] = {0.0f, 0.0f};
        for (int j = 0; j < 8; j++) {
            c *= dval / (float)(k0 + j + 1);
            #pragma unroll
            for (int e = 0; e < 2; e++) {
                float u = u0[j*512 + e] + u0[PU + j*512 + e];
                float term = c * u;
                tlast[e] = term;
                y[e] += term;
            }
        }
        if (iter == 0) {
            #pragma unroll
            for (int e = 0; e < 2; e++) {
                bf16 h = __float2bfloat16_rn(tlast[e]);
                th[idx0 + e] = h;
                tl[idx0 + e] = __float2bfloat16_rn(tlast[e] - __bfloat162float(h));
            }
            grid_barrier(&g_gen1, &g_cnt1, 256);
        } else {
            #pragma unroll
            for (int e = 0; e < 2; e++) {
                float yy = y[e] + dval * bx[idx0 + e];
                out_hssm[idx0 + e] = yy;
                bf16 h = __float2bfloat16_rn(yy);
                hsh[idx0 + e] = h;
                hsl[idx0 + e] = __float2bfloat16_rn(yy - __bfloat162float(h));
                __half hx = __float2half_rn(yy);
                __half lx = __float2half_rn(yy - __half2float(hx));
                *(uint16_t*)&hs16h[idx0 + e] = *(uint16_t*)&hx;
                *(uint16_t*)&hs16l[idx0 + e] = *(uint16_t*)&lx;
            }
        }
    }
}

// ========================= persistent tail kernel ============================
// 256 blocks: [q sK4 (64, bf16) + hssm-proj sK4 (64, fp16)] -> barrier ->
// attn -> barrier -> [ctx@M sK4 (64, fp16)] -> barrier -> proj(14)+LN.
__global__ void __launch_bounds__(256, 2)
tail_kernel(const bf16* __restrict__ hsh, const bf16* __restrict__ hsl,
            const bf16* __restrict__ hs16h, const bf16* __restrict__ hs16l,
            const bf16* __restrict__ aiwh, const bf16* __restrict__ aiwl,
            const bf16* __restrict__ pw16h, const bf16* __restrict__ pw16l,
            const bf16* __restrict__ m16h, const bf16* __restrict__ m16l,
            float* __restrict__ qp, float* __restrict__ kvp,
            float* __restrict__ part,
            const float* __restrict__ attn_in_b,
            bf16* __restrict__ cx16h, bf16* __restrict__ cx16l,
            const float* __restrict__ pvec,
            const float* __restrict__ pg, const float* __restrict__ pbe,
            float* __restrict__ out_y)
{
    extern __shared__ char smem[];
    const int tid = threadIdx.x;
    const int blk = blockIdx.x;

    // ---- phase A ----
    if (blk < 128) {
        GTask T = {};
        T.nsplit = NOSPLIT; T.mtiles = 2; T.K = 128;
        if (blk < 64) {                 // q split-K4 (bf16 3-product)
            int kz = blk >> 4;
            T.Xhi = hsh; T.Xlo = hsl; T.ldX = DD;
            T.Whi = aiwh; T.Wlo = aiwl; T.ldW = DD;
            T.C = qp + (long)kz*BB*DD; T.ldC = DD; T.kofs = kz*128;
            gemm_tile(T, blk & 15, smem);
        } else {                        // hssm proj split-K4 (fp16 2-product)
            int b2 = blk - 64;
            int kz = b2 >> 4;
            T.Xhi = hs16h; T.Xlo = hs16l; T.ldX = DD;
            T.Whi = pw16h; T.Wlo = pw16l; T.ldW = 5*DD;
            T.C = part + (long)kz*BB*DD; T.ldC = DD; T.kofs = kz*128;
            T.fp2 = 1;
            gemm_tile(T, b2 & 15, smem);
        }
    }
    grid_barrier(&g_gen2, &g_cnt2, 256);

    // ---- phase B: attention (block = batch) ----
    {
        int b    = blk;
        int warp = tid >> 5;
        int lane = tid & 31;
        const long QP = (long)BB*DD;
        const long KP = (long)SS*BB*2*DD;

        long qo = (long)b * DD + warp * 64;
        float q0 = attn_in_b[warp*64 + lane];
        float q1 = attn_in_b[warp*64 + lane + 32];
        #pragma unroll
        for (int p = 0; p < 4; p++) {
            q0 += qp[p*QP + qo + lane];
            q1 += qp[p*QP + qo + lane + 32];
        }

        float sc[SS];
        #pragma unroll
        for (int s = 0; s < SS; s++) {
            long ko = (long)(s*BB + b) * 1024 + warp * 64;
            float k0 = kvp[ko + lane]      + kvp[KP + ko + lane]
                     + attn_in_b[512 + warp*64 + lane];
            float k1 = kvp[ko + lane + 32] + kvp[KP + ko + lane + 32]
                     + attn_in_b[512 + warp*64 + lane + 32];
            float d = q0 * k0 + q1 * k1;
            #pragma unroll
            for (int o = 16; o > 0; o >>= 1) d += __shfl_xor_sync(0xffffffff, d, o);
            sc[s] = d * 0.125f;
        }
        float m = fmaxf(sc[0], fmaxf(sc[1], sc[2]));
        float e[SS], sum = 0.0f;
        #pragma unroll
        for (int s = 0; s < SS; s++) { e[s] = expf(sc[s] - m); sum += e[s]; }
        float inv = 1.0f / sum;

        float c0 = 0.0f, c1 = 0.0f;
        #pragma unroll
        for (int s = 0; s < SS; s++) {
            long vo = (long)(s*BB + b) * 1024 + 512 + warp * 64;
            float v0 = kvp[vo + lane]      + kvp[KP + vo + lane]
                     + attn_in_b[1024 + warp*64 + lane];
            float v1 = kvp[vo + lane + 32] + kvp[KP + vo + lane + 32]
                     + attn_in_b[1024 + warp*64 + lane + 32];
            float w = e[s] * inv;
            c0 += w * v0;
            c1 += w * v1;
        }
        long o0 = (long)b * DD + warp*64 + lane;
        __half h0 = __float2half_rn(c0);
        __half h1 = __float2half_rn(c1);
        __half l0 = __float2half_rn(c0 - __half2float(h0));
        __half l1 = __float2half_rn(c1 - __half2float(h1));
        *(uint16_t*)&cx16h[o0]      = *(uint16_t*)&h0;
        *(uint16_t*)&cx16l[o0]      = *(uint16_t*)&l0;
        *(uint16_t*)&cx16h[o0 + 32] = *(uint16_t*)&h1;
        *(uint16_t*)&cx16l[o0 + 32] = *(uint16_t*)&l1;
    }
    grid_barrier(&g_gen2, &g_cnt2, 256);

    // ---- phase C: ctx @ M split-K4 (64 blk, fp16) -> part planes 4..7 ----
    if (blk < 64) {
        int kz = blk >> 4;
        GTask T = {};
        T.Xhi = cx16h; T.Xlo = cx16l; T.ldX = DD;
        T.Whi = m16h; T.Wlo = m16l; T.ldW = DD;
        T.C = part + (long)(4+kz)*BB*DD; T.ldC = DD;
        T.K = 128; T.kofs = kz*128; T.nsplit = NOSPLIT; T.mtiles = 2;
        T.fp2 = 1;
        gemm_tile(T, blk & 15, smem);
    }
    grid_barrier(&g_gen2, &g_cnt2, 256);

    // ---- phase D: proj reduce (14 planes) + LN ----
    {
        float* red = (float*)smem;
        int row = blk, t = tid;
        long o0 = (long)row*DD + t, o1 = o0 + 256;
        const long PL = (long)BB*DD;
        float x0 = pvec[t], x1 = pvec[t+256];
        #pragma unroll
        for (int p = 0; p < 14; p++) { x0 += part[p*PL + o0]; x1 += part[p*PL + o1]; }

        red[t] = x0 + x1; __syncthreads();
        for (int o = 128; o > 0; o >>= 1) { if (t < o) red[t] += red[t+o]; __syncthreads(); }
        float mean = red[0] * (1.0f/DD);
        __syncthreads();

        float d0 = x0 - mean, d1 = x1 - mean;
        red[t] = d0*d0 + d1*d1; __syncthreads();
        for (int o = 128; o > 0; o >>= 1) { if (t < o) red[t] += red[t+o]; __syncthreads(); }
        float inv = rsqrtf(red[0] * (1.0f/DD) + 1e-5f);

        out_y[o0] = d0 * inv * pg[t]     + pbe[t];
        out_y[o1] = d1 * inv * pg[t+256] + pbe[t+256];
    }
}

// ---------------------------------------------------------------------------
static inline GTask mk_task(const bf16* Xhi, const bf16* Xlo, int ldX,
                            const bf16* Whi, const bf16* Wlo, int ldW,
                            float* C, int ldC, int K, int kofs,
                            int mtiles, int ntiles, int fp2 = 0)
{
    GTask t = {};
    t.Xhi = Xhi; t.Xlo = Xlo; t.ldX = ldX;
    t.Whi = Whi; t.Wlo = Wlo; t.ldW = ldW;
    t.C = C; t.ldC = ldC;
    t.K = K; t.kofs = kofs; t.nsplit = NOSPLIT;
    t.mtiles = mtiles; t.blocks = mtiles*ntiles;
    t.fp2 = fp2;
    return t;
}

extern "C" void kernel_launch(void* const* d_in, const int* in_sizes, int n_in,
                              void* d_out, int out_size)
{
    (void)in_sizes; (void)n_in; (void)out_size;

    const float* x        = (const float*)d_in[0];
    const float* h_prev   = (const float*)d_in[1];
    const float* lstm_h   = (const float*)d_in[2];
    const float* lstm_c   = (const float*)d_in[3];
    const float* A        = (const float*)d_in[4];
    const float* Bm       = (const float*)d_in[5];
    const float* dn_w1    = (const float*)d_in[6];
    const float* dn_b1    = (const float*)d_in[7];
    const float* dn_g     = (const float*)d_in[8];
    const float* dn_beta  = (const float*)d_in[9];
    const float* dn_w2    = (const float*)d_in[10];
    const float* dn_b2    = (const float*)d_in[11];
    const float* lstm_wih = (const float*)d_in[12];
    const float* lstm_whh = (const float*)d_in[13];
    const float* lstm_bih = (const float*)d_in[14];
    const float* lstm_bhh = (const float*)d_in[15];
    const float* decays   = (const float*)d_in[16];
    const float* attn_in_w  = (const float*)d_in[17];
    const float* attn_in_b  = (const float*)d_in[18];
    const float* attn_out_w = (const float*)d_in[19];
    const float* attn_out_b = (const float*)d_in[20];
    const float* proj_w   = (const float*)d_in[21];
    const float* proj_b   = (const float*)d_in[22];
    const float* proj_g   = (const float*)d_in[23];
    const float* proj_beta= (const float*)d_in[24];

    float* out = (float*)d_out;
    float* out_y    = out;
    float* out_hssm = out + BB*DD;
    float* out_hnew = out + 2*BB*DD;
    float* out_cnew = out + 2*BB*DD + SS*BB*DD;

    float *p_h1, *p_delta, *p_bx, *p_U, *p_gA, *p_gB, *p_kvp, *p_qp, *p_part, *p_pvec;
    cudaGetSymbolAddress((void**)&p_h1,    g_h1);
    cudaGetSymbolAddress((void**)&p_delta, g_delta);
    cudaGetSymbolAddress((void**)&p_bx,    g_bx);
    cudaGetSymbolAddress((void**)&p_U,     g_U);
    cudaGetSymbolAddress((void**)&p_gA,    g_gA);
    cudaGetSymbolAddress((void**)&p_gB,    g_gB);
    cudaGetSymbolAddress((void**)&p_kvp,   g_kvp);
    cudaGetSymbolAddress((void**)&p_qp,    g_qp);
    cudaGetSymbolAddress((void**)&p_part,  g_part);
    cudaGetSymbolAddress((void**)&p_pvec,  g_pvec);

    bf16 *xh,*xl,*hph,*hpl,*w1h,*w1l,*bmh,*bml,*aiwh,*aiwl,*wpowh,*wpowl,
         *ath,*atl,*a2th,*a2tl,*a4th,*a4tl,*th,*tl,*hsh,*hsl,*hnh,*hnl;
    bf16 *x16h,*x16l,*lh16h,*lh16l,*wih16h,*wih16l,*whh16h,*whh16l,
         *pw16h,*pw16l,*aot16h,*aot16l,*m16h,*m16l,*hs16h,*hs16l,
         *hn16h,*hn16l,*cx16h,*cx16l;
    cudaGetSymbolAddress((void**)&xh, g_xh);     cudaGetSymbolAddress((void**)&xl, g_xl);
    cudaGetSymbolAddress((void**)&hph, g_hph);   cudaGetSymbolAddress((void**)&hpl, g_hpl);
    cudaGetSymbolAddress((void**)&w1h, g_w1h);   cudaGetSymbolAddress((void**)&w1l, g_w1l);
    cudaGetSymbolAddress((void**)&bmh, g_bmh);   cudaGetSymbolAddress((void**)&bml, g_bml);
    cudaGetSymbolAddress((void**)&aiwh, g_aiwh); cudaGetSymbolAddress((void**)&aiwl, g_aiwl);
    cudaGetSymbolAddress((void**)&wpowh, g_wpowh); cudaGetSymbolAddress((void**)&wpowl, g_wpowl);
    cudaGetSymbolAddress((void**)&ath, g_ath);   cudaGetSymbolAddress((void**)&atl, g_atl);
    cudaGetSymbolAddress((void**)&a2th, g_a2th); cudaGetSymbolAddress((void**)&a2tl, g_a2tl);
    cudaGetSymbolAddress((void**)&a4th, g_a4th); cudaGetSymbolAddress((void**)&a4tl, g_a4tl);
    cudaGetSymbolAddress((void**)&th, g_th);     cudaGetSymbolAddress((void**)&tl, g_tl);
    cudaGetSymbolAddress((void**)&hsh, g_hsh);   cudaGetSymbolAddress((void**)&hsl, g_hsl);
    cudaGetSymbolAddress((void**)&hnh, g_hnh);   cudaGetSymbolAddress((void**)&hnl, g_hnl);
    cudaGetSymbolAddress((void**)&x16h, g_x16h);   cudaGetSymbolAddress((void**)&x16l, g_x16l);
    cudaGetSymbolAddress((void**)&lh16h, g_lh16h); cudaGetSymbolAddress((void**)&lh16l, g_lh16l);
    cudaGetSymbolAddress((void**)&wih16h, g_wih16h); cudaGetSymbolAddress((void**)&wih16l, g_wih16l);
    cudaGetSymbolAddress((void**)&whh16h, g_whh16h); cudaGetSymbolAddress((void**)&whh16l, g_whh16l);
    cudaGetSymbolAddress((void**)&pw16h, g_pw16h);   cudaGetSymbolAddress((void**)&pw16l, g_pw16l);
    cudaGetSymbolAddress((void**)&aot16h, g_aot16h); cudaGetSymbolAddress((void**)&aot16l, g_aot16l);
    cudaGetSymbolAddress((void**)&m16h, g_m16h);     cudaGetSymbolAddress((void**)&m16l, g_m16l);
    cudaGetSymbolAddress((void**)&hs16h, g_hs16h);   cudaGetSymbolAddress((void**)&hs16l, g_hs16l);
    cudaGetSymbolAddress((void**)&hn16h, g_hn16h);   cudaGetSymbolAddress((void**)&hn16l, g_hn16l);
    cudaGetSymbolAddress((void**)&cx16h, g_cx16h);   cudaGetSymbolAddress((void**)&cx16l, g_cx16l);

    cudaFuncSetAttribute(gemm_mma,
        cudaFuncAttributeMaxDynamicSharedMemorySize, SMEM_SZ);
    cudaFuncSetAttribute(chain_kernel,
        cudaFuncAttributeMaxDynamicSharedMemorySize, SMEM_SZ);
    cudaFuncSetAttribute(tail_kernel,
        cudaFuncAttributeMaxDynamicSharedMemorySize, SMEM_SZ);

    const long W2 = (long)DD*DD;
    const long KP = (long)SS*BB*2*DD;

    // ---- K1: split all operands + transposes ----
    {
        STaskSet st = {};
        auto add = [&](int i, const float* s, bf16* h, bf16* l, long n, int hf) {
            st.t[i] = { s, h, l, (int)(n / 2048), hf };
        };
        add(0,  x,        xh,     xl,     (long)BB*DD, 0);
        add(1,  x,        x16h,   x16l,   (long)BB*DD, 1);
        add(2,  h_prev,   hph,    hpl,    (long)BB*DD, 0);
        add(3,  lstm_h,   lh16h,  lh16l,  (long)SS*BB*DD, 1);
        add(4,  dn_w1,    w1h,    w1l,    W2, 0);
        add(5,  Bm,       bmh,    bml,    W2, 0);
        add(6,  lstm_wih, wih16h, wih16l, (long)SS*4*W2, 1);
        add(7,  lstm_whh, whh16h, whh16l, (long)SS*4*W2, 1);
        add(8,  attn_in_w, aiwh,  aiwl,   3*W2, 0);
        add(9,  proj_w,   pw16h,  pw16l,  5*W2, 1);
        add(10, A,        wpowh,  wpowl,  W2, 0);
        st.ntasks = 11;
        int total = 0;
        for (int i = 0; i < 11; i++) total += st.t[i].blocks;
        prep_kernel<<<total + 512, 256>>>(st, total,
            A, ath, atl, attn_out_w, aot16h, aot16l);
    }

    // ---- K2 (G1, 480 blocks): h1|bx (bf16), 6 lstm (fp16), A^2 (bf16), M (fp16) ----
    {
        GTaskSet ts = {};
        GTask t0 = mk_task(xh, xl, DD, w1h, w1l, DD, p_h1, DD, DD, 0, 2, 16);
        t0.bias = dn_b1; t0.Wn2hi = bmh; t0.Wn2lo = bml;
        t0.Cn2 = p_bx; t0.ldCn2 = DD; t0.nsplit = DD;
        ts.t[0] = t0;
        for (int s = 0; s < SS; s++) {
            ts.t[1+s] = mk_task(x16h, x16l, DD,
                                wih16h + (long)s*4*W2, wih16l + (long)s*4*W2, DD,
                                p_gA + (long)s*BB*4*DD, 4*DD, DD, 0, 2, 32, 1);
            ts.t[4+s] = mk_task(lh16h + (long)s*BB*DD, lh16l + (long)s*BB*DD, DD,
                                whh16h + (long)s*4*W2, whh16l + (long)s*4*W2, DD,
                                p_gB + (long)s*BB*4*DD, 4*DD, DD, 0, 2, 32, 1);
        }
        GTask ta = mk_task(wpowh, wpowl, DD, ath, atl, DD, nullptr, DD, DD, 0, 4, 8);
        ta.Chi = wpowh + W2; ta.Clo = wpowl + W2;
        ta.Cthi = a2th; ta.Ctlo = a2tl; ta.ldCt = DD;
        ts.t[7] = ta;
        GTask tm = mk_task(pw16h + 512, pw16l + 512, 5*DD, aot16h, aot16l, DD,
                           nullptr, DD, DD, 0, 4, 8, 1);
        tm.Chi = m16h; tm.Clo = m16l;
        ts.t[8] = tm;
        ts.ntasks = 9;
        gemm_mma<<<480, 256, SMEM_SZ>>>(ts);
    }

    // ---- K3: S1 fused ----
    s1_kernel<<<2304, 256>>>(p_h1, dn_g, dn_beta, dn_w2, dn_b2, p_delta,
                             proj_w, attn_out_b, proj_b, p_pvec,
                             p_gA, p_gB, lstm_bih, lstm_bhh, lstm_c, decays,
                             out_hnew, out_cnew, hnh, hnl, hn16h, hn16l);

    // ---- K4 (G2, 256 blocks): A^3, A^4 (+A4T), kv split-K-2 (all bf16) ----
    {
        GTaskSet ts = {};
        GTask t3 = mk_task(wpowh + W2, wpowl + W2, DD, ath, atl, DD,
                           nullptr, DD, DD, 0, 4, 8);
        t3.Chi = wpowh + 2*W2; t3.Clo = wpowl + 2*W2;
        ts.t[0] = t3;
        GTask t4 = mk_task(wpowh + W2, wpowl + W2, DD, a2th, a2tl, DD,
                           nullptr, DD, DD, 0, 4, 8);
        t4.Chi = wpowh + 3*W2; t4.Clo = wpowl + 3*W2;
        t4.Cthi = a4th; t4.Ctlo = a4tl; t4.ldCt = DD;
        ts.t[1] = t4;
        for (int kz = 0; kz < 2; kz++)
            ts.t[2+kz] = mk_task(hnh, hnl, DD, aiwh + W2, aiwl + W2, DD,
                                 p_kvp + (long)kz*KP, 2*DD, 256, kz*256, 6, 16);
        ts.ntasks = 4;
        gemm_mma<<<256, 256, SMEM_SZ>>>(ts);
    }

    // ---- K5 (224 blocks): A^5..A^8 (bf16), hnew proj (fp16, planes 8..13) ----
    {
        GTaskSet ts = {};
        GTask t5 = mk_task(wpowh + 3*W2, wpowl + 3*W2, DD, ath, atl, DD,
                           nullptr, DD, DD, 0, 4, 8);
        t5.Chi = wpowh + 4*W2; t5.Clo = wpowl + 4*W2;
        ts.t[0] = t5;
        GTask t6 = mk_task(wpowh + 3*W2, wpowl + 3*W2, DD, a2th, a2tl, DD,
                           nullptr, DD, DD, 0, 4, 8);
        t6.Chi = wpowh + 5*W2; t6.Clo = wpowl + 5*W2;
        ts.t[1] = t6;
        GTask t7 = mk_task(wpowh + 2*W2, wpowl + 2*W2, DD, a4th, a4tl, DD,
                           nullptr, DD, DD, 0, 4, 8);
        t7.Chi = wpowh + 6*W2; t7.Clo = wpowl + 6*W2;
        ts.t[2] = t7;
        GTask t8 = mk_task(wpowh + 3*W2, wpowl + 3*W2, DD, a4th, a4tl, DD,
                           nullptr, DD, DD, 0, 4, 8);
        t8.Chi = wpowh + 7*W2; t8.Clo = wpowl + 7*W2;
        ts.t[3] = t8;
        int p = 0;
        for (int i = 0; i < SS; i++)
            for (int kz = 0; kz < 2; kz++, p++)
                ts.t[4+p] = mk_task(hn16h + (long)i*BB*DD, hn16l + (long)i*BB*DD, DD,
                                    pw16h + 1024 + i*512, pw16l + 1024 + i*512, 5*DD,
                                    p_part + (long)(8 + p)*BB*DD, DD,
                                    256, kz*256, 2, 8, 1);
        ts.ntasks = 10;
        gemm_mma<<<224, 256, SMEM_SZ>>>(ts);
    }

    // ---- K6: persistent chain (split-K-2, 256 blocks, bf16) ----
    chain_kernel<<<256, 256, SMEM_SZ>>>(hph, hpl, wpowh, wpowl, p_U, th, tl,
                                        p_delta, h_prev, p_bx,
                                        out_hssm, hsh, hsl, hs16h, hs16l);

    // ---- K7: persistent tail ----
    tail_kernel<<<256, 256, SMEM_SZ>>>(hsh, hsl, hs16h, hs16l,
                                       aiwh, aiwl, pw16h, pw16l, m16h, m16l,
                                       p_qp, p_kvp, p_part, attn_in_b,
                                       cx16h, cx16l, p_pvec, proj_g, proj_beta,
                                       out_y);
}

// round 17
// speedup vs baseline: 1.1552x; 1.0336x over previous
#include <cuda_runtime.h>
#include <cuda_bf16.h>
#include <cuda_fp16.h>
#include <math.h>
#include <cstdint>

// ---------------------------------------------------------------------------
// SSMXLSTMFusion: D=512, S=3, BATCH=256, H=8, HD=64
// Round 17: R16 + chain GEMMs in fp16 2-product (uniform launch; Wpow kept in
// BOTH bf16 [for A-power construction, 3-product] and fp16 [for chain] via
// dual-write epilogues) + K2 task reorder (slow bf16 tasks first).
// ---------------------------------------------------------------------------

#define DD    512
#define BB    256
#define SS    3
typedef __nv_bfloat16 bf16;

// ------------------------- fp32 scratch ------------------------------------
__device__ float g_h1   [BB*DD];
__device__ float g_delta[BB];
__device__ float g_bx   [BB*DD];
__device__ float g_U    [2*BB*8*DD];
__device__ float g_gA   [SS*BB*4*DD];
__device__ float g_gB   [SS*BB*4*DD];
__device__ float g_kvp  [2*SS*BB*2*DD];
__device__ float g_qp   [4*BB*DD];
__device__ float g_part [14*BB*DD];           // hssm 0-3, ctx 4-7, hnew 8-13
__device__ float g_pvec [DD];

// ------------------------- bf16 hi/lo planes (3-product path) ---------------
__device__ bf16 g_xh[BB*DD],          g_xl[BB*DD];
__device__ bf16 g_w1h[DD*DD],         g_w1l[DD*DD];
__device__ bf16 g_bmh[DD*DD],         g_bml[DD*DD];
__device__ bf16 g_aiwh[3*DD*DD],      g_aiwl[3*DD*DD];
__device__ bf16 g_wpowh[8*DD*DD],     g_wpowl[8*DD*DD];    // A^1..A^8 (bf16)
__device__ bf16 g_ath[DD*DD],         g_atl[DD*DD];
__device__ bf16 g_a2th[DD*DD],        g_a2tl[DD*DD];
__device__ bf16 g_a4th[DD*DD],        g_a4tl[DD*DD];
__device__ bf16 g_hsh[BB*DD],         g_hsl[BB*DD];
__device__ bf16 g_hnh[SS*BB*DD],      g_hnl[SS*BB*DD];

// ------------------------- fp16 hi/lo planes (2-product path, bit-stored) ---
__device__ bf16 g_x16h[BB*DD],        g_x16l[BB*DD];
__device__ bf16 g_hp16h[BB*DD],       g_hp16l[BB*DD];      // h_prev (fp16)
__device__ bf16 g_wpow16h[8*DD*DD],   g_wpow16l[8*DD*DD];  // A^1..A^8 (fp16)
__device__ bf16 g_t16h[BB*DD],        g_t16l[BB*DD];       // chain T (fp16)
__device__ bf16 g_lh16h[SS*BB*DD],    g_lh16l[SS*BB*DD];
__device__ bf16 g_wih16h[SS*4*DD*DD], g_wih16l[SS*4*DD*DD];
__device__ bf16 g_whh16h[SS*4*DD*DD], g_whh16l[SS*4*DD*DD];
__device__ bf16 g_pw16h[DD*5*DD],     g_pw16l[DD*5*DD];
__device__ bf16 g_aot16h[DD*DD],      g_aot16l[DD*DD];
__device__ bf16 g_m16h[DD*DD],        g_m16l[DD*DD];
__device__ bf16 g_hs16h[BB*DD],       g_hs16l[BB*DD];
__device__ bf16 g_hn16h[SS*BB*DD],    g_hn16l[SS*BB*DD];
__device__ bf16 g_cx16h[BB*DD],       g_cx16l[BB*DD];

__device__ volatile unsigned g_gen1; __device__ unsigned g_cnt1;
__device__ volatile unsigned g_gen2; __device__ unsigned g_cnt2;

// ========================= descriptors ======================================
struct GTask {
    const bf16 *Xhi, *Xlo, *Whi, *Wlo, *Wn2hi, *Wn2lo;
    const float* bias;
    float *C, *Cn2;
    bf16 *Chi, *Clo, *Cthi, *Ctlo;
    bf16 *Dhi, *Dlo;                       // optional fp16 dual-write
    int ldX, ldW, ldC, ldCn2, ldCt;
    int K, kofs, nsplit, mtiles, blocks, fp2;
};
struct GTaskSet { GTask t[12]; int ntasks; };

struct STask { const float* src; bf16 *hi, *lo; int blocks; int half; };
struct STaskSet { STask t[12]; int ntasks; };

#define NOSPLIT (1<<30)

// ========================= smem layout ======================================
#define RSB     80
#define OFF_AHI 0
#define OFF_ALO 10240
#define OFF_BHI 20480
#define OFF_BLO 25600
#define STAGE   30720
#define SMEM_SZ (3*STAGE)      // 92160 bytes

__device__ __forceinline__ uint32_t smem_to_u32(const void* p) {
    uint32_t a;
    asm("{ .reg .u64 t; cvta.to.shared.u64 t, %1; cvt.u32.u64 %0, t; }"
        : "=r"(a) : "l"(p));
    return a;
}

__device__ __forceinline__ uint32_t pk2(bf16 a, bf16 b) {
    uint16_t ua = *(uint16_t*)&a, ub = *(uint16_t*)&b;
    return (uint32_t)ua | ((uint32_t)ub << 16);
}
__device__ __forceinline__ uint32_t pk2h(__half a, __half b) {
    uint16_t ua = *(uint16_t*)&a, ub = *(uint16_t*)&b;
    return (uint32_t)ua | ((uint32_t)ub << 16);
}

__device__ __forceinline__ void split8(float4 u, float4 v, uint4& hi, uint4& lo)
{
    float f[8] = {u.x,u.y,u.z,u.w,v.x,v.y,v.z,v.w};
    uint32_t h[4], l[4];
    #pragma unroll
    for (int i = 0; i < 4; i++) {
        bf16 b0 = __float2bfloat16_rn(f[2*i]);
        bf16 b1 = __float2bfloat16_rn(f[2*i+1]);
        bf16 r0 = __float2bfloat16_rn(f[2*i]   - __bfloat162float(b0));
        bf16 r1 = __float2bfloat16_rn(f[2*i+1] - __bfloat162float(b1));
        h[i] = pk2(b0, b1);
        l[i] = pk2(r0, r1);
    }
    hi = make_uint4(h[0], h[1], h[2], h[3]);
    lo = make_uint4(l[0], l[1], l[2], l[3]);
}

__device__ __forceinline__ void split8h(float4 u, float4 v, uint4& hi, uint4& lo)
{
    float f[8] = {u.x,u.y,u.z,u.w,v.x,v.y,v.z,v.w};
    uint32_t h[4], l[4];
    #pragma unroll
    for (int i = 0; i < 4; i++) {
        __half b0 = __float2half_rn(f[2*i]);
        __half b1 = __float2half_rn(f[2*i+1]);
        __half r0 = __float2half_rn(f[2*i]   - __half2float(b0));
        __half r1 = __float2half_rn(f[2*i+1] - __half2float(b1));
        h[i] = pk2h(b0, b1);
        l[i] = pk2h(r0, r1);
    }
    hi = make_uint4(h[0], h[1], h[2], h[3]);
    lo = make_uint4(l[0], l[1], l[2], l[3]);
}

__device__ __forceinline__ void ldm_x4(uint32_t* r, uint32_t addr) {
    asm volatile("ldmatrix.sync.aligned.m8n8.x4.shared.b16 {%0,%1,%2,%3}, [%4];"
        : "=r"(r[0]), "=r"(r[1]), "=r"(r[2]), "=r"(r[3]) : "r"(addr));
}

__device__ __forceinline__ void mma_bf16(float* c, const uint32_t* a, const uint32_t* b)
{
    asm volatile(
        "mma.sync.aligned.m16n8k16.row.col.f32.bf16.bf16.f32 "
        "{%0,%1,%2,%3}, {%4,%5,%6,%7}, {%8,%9}, {%0,%1,%2,%3};"
        : "+f"(c[0]), "+f"(c[1]), "+f"(c[2]), "+f"(c[3])
        : "r"(a[0]), "r"(a[1]), "r"(a[2]), "r"(a[3]), "r"(b[0]), "r"(b[1]));
}

__device__ __forceinline__ void mma_f16(float* c, const uint32_t* a, const uint32_t* b)
{
    asm volatile(
        "mma.sync.aligned.m16n8k16.row.col.f32.f16.f16.f32 "
        "{%0,%1,%2,%3}, {%4,%5,%6,%7}, {%8,%9}, {%0,%1,%2,%3};"
        : "+f"(c[0]), "+f"(c[1]), "+f"(c[2]), "+f"(c[3])
        : "r"(a[0]), "r"(a[1]), "r"(a[2]), "r"(a[3]), "r"(b[0]), "r"(b[1]));
}

#define CP16(saddr, gaddr) \
    asm volatile("cp.async.cg.shared.global [%0], [%1], 16;" \
        :: "r"(saddr), "l"(gaddr) : "memory")

__device__ __forceinline__ void grid_barrier(volatile unsigned* gen,
                                             unsigned* cnt, unsigned total)
{
    __syncthreads();
    if (threadIdx.x == 0) {
        unsigned mygen = *gen;
        __threadfence();
        unsigned t = atomicAdd(cnt, 1u);
        if (t == total - 1) {
            *cnt = 0;
            __threadfence();
            *gen = mygen + 1;
        } else {
            while (*gen == mygen) { __nanosleep(32); }
            __threadfence();
        }
    }
    __syncthreads();
}

// ------------------------- GEMM tile (device) --------------------------------
__device__ __forceinline__ void issue_chunk(const GTask& T, uint32_t smb,
    int m0, int n0, int tid, int k0, int stage)
{
    const uint32_t sb = smb + (uint32_t)(stage * STAGE);
    #pragma unroll
    for (int j = 0; j < 4; j++) {
        int o  = tid + j*256;
        int pl = o >> 9;
        int r  = (o >> 2) & 127;
        int s  = o & 3;
        const bf16* g = (pl ? T.Xlo : T.Xhi) + (long)(m0 + r) * T.ldX + k0 + s*8;
        uint32_t sa = sb + (uint32_t)(pl*10240 + r*80 + s*16);
        CP16(sa, g);
    }
    #pragma unroll
    for (int j = 0; j < 2; j++) {
        int o  = tid + j*256;
        int pl = o >> 8;
        int r  = (o >> 2) & 63;
        int s  = o & 3;
        int ng = n0 + r;
        const bf16* w;
        if (ng >= T.nsplit)
            w = (pl ? T.Wn2lo : T.Wn2hi) + (long)(ng - T.nsplit) * T.ldW;
        else
            w = (pl ? T.Wlo : T.Whi) + (long)ng * T.ldW;
        uint32_t sa = sb + (uint32_t)(20480 + pl*5120 + r*80 + s*16);
        CP16(sa, w + k0 + s*8);
    }
    asm volatile("cp.async.commit_group;" ::: "memory");
}

__device__ void gemm_tile(const GTask& T, int b, char* smem)
{
    const int m0 = (b % T.mtiles) * 128;
    const int n0 = (b / T.mtiles) * 64;

    const int tid = threadIdx.x;
    const int lid = tid & 31;
    const int wid = tid >> 5;
    const int m_base = (wid & 3) * 32;
    const int n_base = (wid >> 2) * 32;
    const int gid = lid >> 2;
    const int tig = lid & 3;
    const int g  = lid >> 3;
    const int ig = lid & 7;

    const uint32_t smb = smem_to_u32(smem);
    const uint32_t a_ad = smb + (uint32_t)((m_base + (g&1)*8 + ig) * RSB + (g>>1)*16);
    const uint32_t b_ad = smb + (uint32_t)((n_base + (g>>1)*8 + ig) * RSB + (g&1)*16);

    float acc[2][4][4];
    #pragma unroll
    for (int i = 0; i < 2; i++)
        #pragma unroll
        for (int j = 0; j < 4; j++)
            #pragma unroll
            for (int k = 0; k < 4; k++) acc[i][j][k] = 0.0f;

    const int nc = T.K >> 5;

    issue_chunk(T, smb, m0, n0, tid, T.kofs, 0);
    if (nc > 1) issue_chunk(T, smb, m0, n0, tid, T.kofs + 32, 1);

    for (int c = 0; c < nc; c++) {
        if (c + 1 < nc)
            asm volatile("cp.async.wait_group 1;" ::: "memory");
        else
            asm volatile("cp.async.wait_group 0;" ::: "memory");
        __syncthreads();

        if (c + 2 < nc)
            issue_chunk(T, smb, m0, n0, tid, T.kofs + (c+2)*32, (c+2)%3);

        const uint32_t sb = (uint32_t)((c % 3) * STAGE);
        if (T.fp2) {
            #pragma unroll
            for (int ks = 0; ks < 2; ks++) {
                const uint32_t kb = sb + ks * 32;
                uint32_t ahi[2][4], alo[2][4], bhi[4][2];
                #pragma unroll
                for (int mt = 0; mt < 2; mt++) {
                    ldm_x4(ahi[mt], a_ad + OFF_AHI + mt*16*RSB + kb);
                    ldm_x4(alo[mt], a_ad + OFF_ALO + mt*16*RSB + kb);
                }
                #pragma unroll
                for (int np = 0; np < 2; np++) {
                    uint32_t r[4];
                    ldm_x4(r, b_ad + OFF_BHI + np*16*RSB + kb);
                    bhi[2*np][0] = r[0]; bhi[2*np][1] = r[1];
                    bhi[2*np+1][0] = r[2]; bhi[2*np+1][1] = r[3];
                }
                #pragma unroll
                for (int mt = 0; mt < 2; mt++)
                    #pragma unroll
                    for (int nt = 0; nt < 4; nt++) {
                        mma_f16(acc[mt][nt], ahi[mt], bhi[nt]);
                        mma_f16(acc[mt][nt], alo[mt], bhi[nt]);
                    }
            }
        } else {
            #pragma unroll
            for (int ks = 0; ks < 2; ks++) {
                const uint32_t kb = sb + ks * 32;
                uint32_t ahi[2][4], alo[2][4], bhi[4][2], blo[4][2];
                #pragma unroll
                for (int mt = 0; mt < 2; mt++) {
                    ldm_x4(ahi[mt], a_ad + OFF_AHI + mt*16*RSB + kb);
                    ldm_x4(alo[mt], a_ad + OFF_ALO + mt*16*RSB + kb);
                }
                #pragma unroll
                for (int np = 0; np < 2; np++) {
                    uint32_t r[4];
                    ldm_x4(r, b_ad + OFF_BHI + np*16*RSB + kb);
                    bhi[2*np][0] = r[0]; bhi[2*np][1] = r[1];
                    bhi[2*np+1][0] = r[2]; bhi[2*np+1][1] = r[3];
                    ldm_x4(r, b_ad + OFF_BLO + np*16*RSB + kb);
                    blo[2*np][0] = r[0]; blo[2*np][1] = r[1];
                    blo[2*np+1][0] = r[2]; blo[2*np+1][1] = r[3];
                }
                #pragma unroll
                for (int mt = 0; mt < 2; mt++)
                    #pragma unroll
                    for (int nt = 0; nt < 4; nt++) {
                        mma_bf16(acc[mt][nt], ahi[mt], bhi[nt]);
                        mma_bf16(acc[mt][nt], ahi[mt], blo[nt]);
                        mma_bf16(acc[mt][nt], alo[mt], bhi[nt]);
                    }
            }
        }
    }

    #pragma unroll
    for (int mt = 0; mt < 2; mt++) {
        #pragma unroll
        for (int nt = 0; nt < 4; nt++) {
            int n = n0 + n_base + nt*8 + tig*2;
            #pragma unroll
            for (int half = 0; half < 2; half++) {
                int mm = m0 + m_base + mt*16 + gid + half*8;
                float v0 = acc[mt][nt][half*2];
                float v1 = acc[mt][nt][half*2 + 1];
                if (T.Cn2 && n >= T.nsplit) {
                    int nn = n - T.nsplit;
                    *(float2*)(T.Cn2 + (long)mm*T.ldCn2 + nn) = make_float2(v0, v1);
                } else {
                    if (T.bias) { v0 += T.bias[n]; v1 += T.bias[n+1]; }
                    if (T.C)
                        *(float2*)(T.C + (long)mm*T.ldC + n) = make_float2(v0, v1);
                    if (T.Chi) {
                        if (T.fp2) {
                            __half h0 = __float2half_rn(v0);
                            __half h1 = __float2half_rn(v1);
                            __half l0 = __float2half_rn(v0 - __half2float(h0));
                            __half l1 = __float2half_rn(v1 - __half2float(h1));
                            *(uint32_t*)(T.Chi + (long)mm*T.ldC + n) = pk2h(h0, h1);
                            *(uint32_t*)(T.Clo + (long)mm*T.ldC + n) = pk2h(l0, l1);
                        } else {
                            bf16 h0 = __float2bfloat16_rn(v0);
                            bf16 h1 = __float2bfloat16_rn(v1);
                            bf16 l0 = __float2bfloat16_rn(v0 - __bfloat162float(h0));
                            bf16 l1 = __float2bfloat16_rn(v1 - __bfloat162float(h1));
                            *(uint32_t*)(T.Chi + (long)mm*T.ldC + n) = pk2(h0, h1);
                            *(uint32_t*)(T.Clo + (long)mm*T.ldC + n) = pk2(l0, l1);
                            if (T.Cthi) {
                                T.Cthi[(long)n*T.ldCt + mm]       = h0;
                                T.Ctlo[(long)n*T.ldCt + mm]       = l0;
                                T.Cthi[(long)(n+1)*T.ldCt + mm]   = h1;
                                T.Ctlo[(long)(n+1)*T.ldCt + mm]   = l1;
                            }
                            if (T.Dhi) {   // fp16 dual-write
                                __half hh0 = __float2half_rn(v0);
                                __half hh1 = __float2half_rn(v1);
                                __half hl0 = __float2half_rn(v0 - __half2float(hh0));
                                __half hl1 = __float2half_rn(v1 - __half2float(hh1));
                                *(uint32_t*)(T.Dhi + (long)mm*T.ldC + n) = pk2h(hh0, hh1);
                                *(uint32_t*)(T.Dlo + (long)mm*T.ldC + n) = pk2h(hl0, hl1);
                            }
                        }
                    }
                }
            }
        }
    }
}

// ========================= batched GEMM launch ==============================
__global__ void __launch_bounds__(256, 2)
gemm_mma(GTaskSet ts)
{
    extern __shared__ char smem[];
    int b = blockIdx.x, ti = 0;
    while (b >= ts.t[ti].blocks) { b -= ts.t[ti].blocks; ti++; }
    gemm_tile(ts.t[ti], b, smem);
}

// ========================= prep: split + transposes =========================
__global__ void prep_kernel(STaskSet ts, int split_blocks,
                            const float* __restrict__ A,
                            bf16* __restrict__ athi, bf16* __restrict__ atlo,
                            const float* __restrict__ B,
                            bf16* __restrict__ bthi, bf16* __restrict__ btlo)
{
    int b = blockIdx.x;
    if (b < split_blocks) {
        int ti = 0;
        while (b >= ts.t[ti].blocks) { b -= ts.t[ti].blocks; ti++; }
        const STask S = ts.t[ti];
        long idx = ((long)b * 256 + threadIdx.x) * 8;
        float4 u = *(const float4*)(S.src + idx);
        float4 v = *(const float4*)(S.src + idx + 4);
        uint4 hi, lo;
        if (S.half) split8h(u, v, hi, lo);
        else        split8(u, v, hi, lo);
        *(uint4*)(S.hi + idx) = hi;
        *(uint4*)(S.lo + idx) = lo;
        return;
    }
    int tb = b - split_blocks;
    int z  = tb >> 8;
    int rem = tb & 255;
    int bx = (rem & 15) * 32, by = (rem >> 4) * 32;
    int tx = threadIdx.x & 31, ty = threadIdx.x >> 5;
    __shared__ float t[32][33];
    const float* src = z ? B : A;
    bf16* dh = z ? bthi : athi;
    bf16* dl = z ? btlo : atlo;
    int x = bx + tx;
    #pragma unroll
    for (int i = 0; i < 32; i += 8) {
        int y = by + ty + i;
        t[ty + i][tx] = src[(long)y*DD + x];
    }
    __syncthreads();
    int xo = by + tx;
    #pragma unroll
    for (int i = 0; i < 32; i += 8) {
        int yo = bx + ty + i;
        float v = t[tx][ty + i];
        if (z) {  // attn_out_w^T -> fp16
            __half h = __float2half_rn(v);
            __half l = __float2half_rn(v - __half2float(h));
            *(uint16_t*)&dh[(long)yo*DD + xo] = *(uint16_t*)&h;
            *(uint16_t*)&dl[(long)yo*DD + xo] = *(uint16_t*)&l;
        } else {  // A^T -> bf16
            bf16 h = __float2bfloat16_rn(v);
            dh[(long)yo*DD + xo] = h;
            dl[(long)yo*DD + xo] = __float2bfloat16_rn(v - __bfloat162float(h));
        }
    }
}

// ========================= S1 fused ==========================================
__device__ __forceinline__ float sigf(float x) { return 1.0f / (1.0f + expf(-x)); }

__global__ void s1_kernel(const float* __restrict__ h1,
                          const float* __restrict__ dn_g,
                          const float* __restrict__ dn_beta,
                          const float* __restrict__ w2,
                          const float* __restrict__ b2,
                          float* __restrict__ delta,
                          const float* __restrict__ proj_w,
                          const float* __restrict__ aob,
                          const float* __restrict__ proj_b,
                          float* __restrict__ pvec,
                          const float* __restrict__ gA,
                          const float* __restrict__ gB,
                          const float* __restrict__ bih,
                          const float* __restrict__ bhh,
                          const float* __restrict__ lstm_c,
                          const float* __restrict__ decays,
                          float* __restrict__ h_new,
                          float* __restrict__ c_new,
                          bf16* __restrict__ hnh,
                          bf16* __restrict__ hnl,
                          bf16* __restrict__ hn16h,
                          bf16* __restrict__ hn16l)
{
    int blk = blockIdx.x, t = threadIdx.x;
    if (blk < 256) {
        __shared__ float red[256];
        int row = blk;
        const float* r = h1 + (long)row * DD;
        float x0 = r[t], x1 = r[t + 256];
        red[t] = x0 + x1; __syncthreads();
        for (int o = 128; o > 0; o >>= 1) { if (t < o) red[t] += red[t+o]; __syncthreads(); }
        float mean = red[0] * (1.0f/DD);
        __syncthreads();
        float d0 = x0 - mean, d1 = x1 - mean;
        red[t] = d0*d0 + d1*d1; __syncthreads();
        for (int o = 128; o > 0; o >>= 1) { if (t < o) red[t] += red[t+o]; __syncthreads(); }
        float inv = rsqrtf(red[0] * (1.0f/DD) + 1e-5f);
        __syncthreads();
        float y0 = d0 * inv * dn_g[t]     + dn_beta[t];
        float y1 = d1 * inv * dn_g[t+256] + dn_beta[t+256];
        y0 = 0.5f * y0 * (1.0f + erff(y0 * 0.70710678118654752f));
        y1 = 0.5f * y1 * (1.0f + erff(y1 * 0.70710678118654752f));
        red[t] = y0*w2[t] + y1*w2[t+256]; __syncthreads();
        for (int o = 128; o > 0; o >>= 1) { if (t < o) red[t] += red[t+o]; __syncthreads(); }
        if (t == 0) {
            float z = red[0] + b2[0];
            delta[row] = (z > 20.0f) ? z : log1pf(expf(z));
        }
    } else if (blk < 768) {
        __shared__ float red[256];
        int row = blk - 256;
        const float* r = proj_w + (long)row * 2560 + 512;
        red[t] = r[t]*aob[t] + r[t+256]*aob[t+256];
        __syncthreads();
        for (int o = 128; o > 0; o >>= 1) { if (t < o) red[t] += red[t+o]; __syncthreads(); }
        if (t == 0) pvec[row] = proj_b[row] + red[0];
    } else {
        int idx = (blk - 768) * 256 + t;
        int s = idx / (BB*DD);
        int r = idx - s * (BB*DD);
        int b = r >> 9;
        int d = r & 511;
        long gbase = ((long)s * BB + b) * 2048;
        const float* a = gA + gbase;
        const float* h = gB + gbase;
        const float* bi = bih + s*2048;
        const float* bh = bhh + s*2048;
        float ip = a[d]      + h[d]      + bi[d]      + bh[d];
        float fp = a[512+d]  + h[512+d]  + bi[512+d]  + bh[512+d];
        float gp = a[1024+d] + h[1024+d] + bi[1024+d] + bh[1024+d];
        float op = a[1536+d] + h[1536+d] + bi[1536+d] + bh[1536+d];
        float i_g = sigf(ip);
        float f_g = sigf(fp);
        float g_g = tanhf(gp);
        float o_g = sigf(op);
        float c   = lstm_c[idx];
        float craw = f_g * c + i_g * g_g;
        float hn   = o_g * tanhf(craw);
        float dec  = decays[s];
        h_new[idx] = hn;
        c_new[idx] = dec * c + (1.0f - dec) * craw;
        bf16 hh = __float2bfloat16_rn(hn);
        hnh[idx] = hh;
        hnl[idx] = __float2bfloat16_rn(hn - __bfloat162float(hh));
        __half hx = __float2half_rn(hn);
        __half lx = __float2half_rn(hn - __half2float(hx));
        *(uint16_t*)&hn16h[idx] = *(uint16_t*)&hx;
        *(uint16_t*)&hn16l[idx] = *(uint16_t*)&lx;
    }
}

// ========================= persistent chain kernel ===========================
// fp16 2-product GEMMs against fp16 Wpow planes.
__global__ void __launch_bounds__(256, 2)
chain_kernel(const bf16* __restrict__ hp16h, const bf16* __restrict__ hp16l,
             const bf16* __restrict__ wpow16h, const bf16* __restrict__ wpow16l,
             float* __restrict__ U,
             bf16* __restrict__ t16h, bf16* __restrict__ t16l,
             const float* __restrict__ delta,
             const float* __restrict__ h_prev,
             const float* __restrict__ bx,
             float* __restrict__ out_hssm,
             bf16* __restrict__ hsh, bf16* __restrict__ hsl,
             bf16* __restrict__ hs16h, bf16* __restrict__ hs16l)
{
    extern __shared__ char smem[];
    const int tid = threadIdx.x;
    const long PU = (long)BB * 8 * DD;
    const long idx0 = ((long)blockIdx.x * 256 + tid) * 2;
    const int row = (int)(idx0 >> 9);
    const int col = (int)(idx0 & 511);
    const float dval = delta[row];

    float y[2];
    y[0] = h_prev[idx0];
    y[1] = h_prev[idx0 + 1];

    for (int iter = 0; iter < 2; iter++) {
        {
            int kz   = blockIdx.x >> 7;
            int tile = blockIdx.x & 127;
            GTask T = {};
            T.Xhi = iter ? t16h : hp16h;  T.Xlo = iter ? t16l : hp16l;  T.ldX = DD;
            T.Whi = wpow16h;              T.Wlo = wpow16l;              T.ldW = DD;
            T.C = U + (long)kz * PU;      T.ldC = 8*DD;
            T.K = 256; T.kofs = kz*256; T.nsplit = NOSPLIT; T.mtiles = 2;
            T.fp2 = 1;
            gemm_tile(T, tile, smem);
        }
        grid_barrier(&g_gen1, &g_cnt1, 256);

        const int k0 = iter * 8;
        const float* u0 = U + (long)row * 4096 + col;
        float c = 1.0f, tlast[2] = {0.0f, 0.0f};
        for (int j = 0; j < 8; j++) {
            c *= dval / (float)(k0 + j + 1);
            #pragma unroll
            for (int e = 0; e < 2; e++) {
                float u = u0[j*512 + e] + u0[PU + j*512 + e];
                float term = c * u;
                tlast[e] = term;
                y[e] += term;
            }
        }
        if (iter == 0) {
            #pragma unroll
            for (int e = 0; e < 2; e++) {
                __half h = __float2half_rn(tlast[e]);
                __half l = __float2half_rn(tlast[e] - __half2float(h));
                *(uint16_t*)&t16h[idx0 + e] = *(uint16_t*)&h;
                *(uint16_t*)&t16l[idx0 + e] = *(uint16_t*)&l;
            }
            grid_barrier(&g_gen1, &g_cnt1, 256);
        } else {
            #pragma unroll
            for (int e = 0; e < 2; e++) {
                float yy = y[e] + dval * bx[idx0 + e];
                out_hssm[idx0 + e] = yy;
                bf16 h = __float2bfloat16_rn(yy);
                hsh[idx0 + e] = h;
                hsl[idx0 + e] = __float2bfloat16_rn(yy - __bfloat162float(h));
                __half hx = __float2half_rn(yy);
                __half lx = __float2half_rn(yy - __half2float(hx));
                *(uint16_t*)&hs16h[idx0 + e] = *(uint16_t*)&hx;
                *(uint16_t*)&hs16l[idx0 + e] = *(uint16_t*)&lx;
            }
        }
    }
}

// ========================= persistent tail kernel ============================
__global__ void __launch_bounds__(256, 2)
tail_kernel(const bf16* __restrict__ hsh, const bf16* __restrict__ hsl,
            const bf16* __restrict__ hs16h, const bf16* __restrict__ hs16l,
            const bf16* __restrict__ aiwh, const bf16* __restrict__ aiwl,
            const bf16* __restrict__ pw16h, const bf16* __restrict__ pw16l,
            const bf16* __restrict__ m16h, const bf16* __restrict__ m16l,
            float* __restrict__ qp, float* __restrict__ kvp,
            float* __restrict__ part,
            const float* __restrict__ attn_in_b,
            bf16* __restrict__ cx16h, bf16* __restrict__ cx16l,
            const float* __restrict__ pvec,
            const float* __restrict__ pg, const float* __restrict__ pbe,
            float* __restrict__ out_y)
{
    extern __shared__ char smem[];
    const int tid = threadIdx.x;
    const int blk = blockIdx.x;

    // ---- phase A ----
    if (blk < 128) {
        GTask T = {};
        T.nsplit = NOSPLIT; T.mtiles = 2; T.K = 128;
        if (blk < 64) {                 // q split-K4 (bf16 3-product)
            int kz = blk >> 4;
            T.Xhi = hsh; T.Xlo = hsl; T.ldX = DD;
            T.Whi = aiwh; T.Wlo = aiwl; T.ldW = DD;
            T.C = qp + (long)kz*BB*DD; T.ldC = DD; T.kofs = kz*128;
            gemm_tile(T, blk & 15, smem);
        } else {                        // hssm proj split-K4 (fp16 2-product)
            int b2 = blk - 64;
            int kz = b2 >> 4;
            T.Xhi = hs16h; T.Xlo = hs16l; T.ldX = DD;
            T.Whi = pw16h; T.Wlo = pw16l; T.ldW = 5*DD;
            T.C = part + (long)kz*BB*DD; T.ldC = DD; T.kofs = kz*128;
            T.fp2 = 1;
            gemm_tile(T, b2 & 15, smem);
        }
    }
    grid_barrier(&g_gen2, &g_cnt2, 256);

    // ---- phase B: attention (block = batch) ----
    {
        int b    = blk;
        int warp = tid >> 5;
        int lane = tid & 31;
        const long QP = (long)BB*DD;
        const long KP = (long)SS*BB*2*DD;

        long qo = (long)b * DD + warp * 64;
        float q0 = attn_in_b[warp*64 + lane];
        float q1 = attn_in_b[warp*64 + lane + 32];
        #pragma unroll
        for (int p = 0; p < 4; p++) {
            q0 += qp[p*QP + qo + lane];
            q1 += qp[p*QP + qo + lane + 32];
        }

        float sc[SS];
        #pragma unroll
        for (int s = 0; s < SS; s++) {
            long ko = (long)(s*BB + b) * 1024 + warp * 64;
            float k0 = kvp[ko + lane]      + kvp[KP + ko + lane]
                     + attn_in_b[512 + warp*64 + lane];
            float k1 = kvp[ko + lane + 32] + kvp[KP + ko + lane + 32]
                     + attn_in_b[512 + warp*64 + lane + 32];
            float d = q0 * k0 + q1 * k1;
            #pragma unroll
            for (int o = 16; o > 0; o >>= 1) d += __shfl_xor_sync(0xffffffff, d, o);
            sc[s] = d * 0.125f;
        }
        float m = fmaxf(sc[0], fmaxf(sc[1], sc[2]));
        float e[SS], sum = 0.0f;
        #pragma unroll
        for (int s = 0; s < SS; s++) { e[s] = expf(sc[s] - m); sum += e[s]; }
        float inv = 1.0f / sum;

        float c0 = 0.0f, c1 = 0.0f;
        #pragma unroll
        for (int s = 0; s < SS; s++) {
            long vo = (long)(s*BB + b) * 1024 + 512 + warp * 64;
            float v0 = kvp[vo + lane]      + kvp[KP + vo + lane]
                     + attn_in_b[1024 + warp*64 + lane];
            float v1 = kvp[vo + lane + 32] + kvp[KP + vo + lane + 32]
                     + attn_in_b[1024 + warp*64 + lane + 32];
            float w = e[s] * inv;
            c0 += w * v0;
            c1 += w * v1;
        }
        long o0 = (long)b * DD + warp*64 + lane;
        __half h0 = __float2half_rn(c0);
        __half h1 = __float2half_rn(c1);
        __half l0 = __float2half_rn(c0 - __half2float(h0));
        __half l1 = __float2half_rn(c1 - __half2float(h1));
        *(uint16_t*)&cx16h[o0]      = *(uint16_t*)&h0;
        *(uint16_t*)&cx16l[o0]      = *(uint16_t*)&l0;
        *(uint16_t*)&cx16h[o0 + 32] = *(uint16_t*)&h1;
        *(uint16_t*)&cx16l[o0 + 32] = *(uint16_t*)&l1;
    }
    grid_barrier(&g_gen2, &g_cnt2, 256);

    // ---- phase C: ctx @ M split-K4 (64 blk, fp16) -> part planes 4..7 ----
    if (blk < 64) {
        int kz = blk >> 4;
        GTask T = {};
        T.Xhi = cx16h; T.Xlo = cx16l; T.ldX = DD;
        T.Whi = m16h; T.Wlo = m16l; T.ldW = DD;
        T.C = part + (long)(4+kz)*BB*DD; T.ldC = DD;
        T.K = 128; T.kofs = kz*128; T.nsplit = NOSPLIT; T.mtiles = 2;
        T.fp2 = 1;
        gemm_tile(T, blk & 15, smem);
    }
    grid_barrier(&g_gen2, &g_cnt2, 256);

    // ---- phase D: proj reduce (14 planes) + LN ----
    {
        float* red = (float*)smem;
        int row = blk, t = tid;
        long o0 = (long)row*DD + t, o1 = o0 + 256;
        const long PL = (long)BB*DD;
        float x0 = pvec[t], x1 = pvec[t+256];
        #pragma unroll
        for (int p = 0; p < 14; p++) { x0 += part[p*PL + o0]; x1 += part[p*PL + o1]; }

        red[t] = x0 + x1; __syncthreads();
        for (int o = 128; o > 0; o >>= 1) { if (t < o) red[t] += red[t+o]; __syncthreads(); }
        float mean = red[0] * (1.0f/DD);
        __syncthreads();

        float d0 = x0 - mean, d1 = x1 - mean;
        red[t] = d0*d0 + d1*d1; __syncthreads();
        for (int o = 128; o > 0; o >>= 1) { if (t < o) red[t] += red[t+o]; __syncthreads(); }
        float inv = rsqrtf(red[0] * (1.0f/DD) + 1e-5f);

        out_y[o0] = d0 * inv * pg[t]     + pbe[t];
        out_y[o1] = d1 * inv * pg[t+256] + pbe[t+256];
    }
}

// ---------------------------------------------------------------------------
static inline GTask mk_task(const bf16* Xhi, const bf16* Xlo, int ldX,
                            const bf16* Whi, const bf16* Wlo, int ldW,
                            float* C, int ldC, int K, int kofs,
                            int mtiles, int ntiles, int fp2 = 0)
{
    GTask t = {};
    t.Xhi = Xhi; t.Xlo = Xlo; t.ldX = ldX;
    t.Whi = Whi; t.Wlo = Wlo; t.ldW = ldW;
    t.C = C; t.ldC = ldC;
    t.K = K; t.kofs = kofs; t.nsplit = NOSPLIT;
    t.mtiles = mtiles; t.blocks = mtiles*ntiles;
    t.fp2 = fp2;
    return t;
}

extern "C" void kernel_launch(void* const* d_in, const int* in_sizes, int n_in,
                              void* d_out, int out_size)
{
    (void)in_sizes; (void)n_in; (void)out_size;

    const float* x        = (const float*)d_in[0];
    const float* h_prev   = (const float*)d_in[1];
    const float* lstm_h   = (const float*)d_in[2];
    const float* lstm_c   = (const float*)d_in[3];
    const float* A        = (const float*)d_in[4];
    const float* Bm       = (const float*)d_in[5];
    const float* dn_w1    = (const float*)d_in[6];
    const float* dn_b1    = (const float*)d_in[7];
    const float* dn_g     = (const float*)d_in[8];
    const float* dn_beta  = (const float*)d_in[9];
    const float* dn_w2    = (const float*)d_in[10];
    const float* dn_b2    = (const float*)d_in[11];
    const float* lstm_wih = (const float*)d_in[12];
    const float* lstm_whh = (const float*)d_in[13];
    const float* lstm_bih = (const float*)d_in[14];
    const float* lstm_bhh = (const float*)d_in[15];
    const float* decays   = (const float*)d_in[16];
    const float* attn_in_w  = (const float*)d_in[17];
    const float* attn_in_b  = (const float*)d_in[18];
    const float* attn_out_w = (const float*)d_in[19];
    const float* attn_out_b = (const float*)d_in[20];
    const float* proj_w   = (const float*)d_in[21];
    const float* proj_b   = (const float*)d_in[22];
    const float* proj_g   = (const float*)d_in[23];
    const float* proj_beta= (const float*)d_in[24];

    float* out = (float*)d_out;
    float* out_y    = out;
    float* out_hssm = out + BB*DD;
    float* out_hnew = out + 2*BB*DD;
    float* out_cnew = out + 2*BB*DD + SS*BB*DD;

    float *p_h1, *p_delta, *p_bx, *p_U, *p_gA, *p_gB, *p_kvp, *p_qp, *p_part, *p_pvec;
    cudaGetSymbolAddress((void**)&p_h1,    g_h1);
    cudaGetSymbolAddress((void**)&p_delta, g_delta);
    cudaGetSymbolAddress((void**)&p_bx,    g_bx);
    cudaGetSymbolAddress((void**)&p_U,     g_U);
    cudaGetSymbolAddress((void**)&p_gA,    g_gA);
    cudaGetSymbolAddress((void**)&p_gB,    g_gB);
    cudaGetSymbolAddress((void**)&p_kvp,   g_kvp);
    cudaGetSymbolAddress((void**)&p_qp,    g_qp);
    cudaGetSymbolAddress((void**)&p_part,  g_part);
    cudaGetSymbolAddress((void**)&p_pvec,  g_pvec);

    bf16 *xh,*xl,*w1h,*w1l,*bmh,*bml,*aiwh,*aiwl,*wpowh,*wpowl,
         *ath,*atl,*a2th,*a2tl,*a4th,*a4tl,*hsh,*hsl,*hnh,*hnl;
    bf16 *x16h,*x16l,*hp16h,*hp16l,*wpow16h,*wpow16l,*t16h,*t16l,
         *lh16h,*lh16l,*wih16h,*wih16l,*whh16h,*whh16l,
         *pw16h,*pw16l,*aot16h,*aot16l,*m16h,*m16l,*hs16h,*hs16l,
         *hn16h,*hn16l,*cx16h,*cx16l;
    cudaGetSymbolAddress((void**)&xh, g_xh);     cudaGetSymbolAddress((void**)&xl, g_xl);
    cudaGetSymbolAddress((void**)&w1h, g_w1h);   cudaGetSymbolAddress((void**)&w1l, g_w1l);
    cudaGetSymbolAddress((void**)&bmh, g_bmh);   cudaGetSymbolAddress((void**)&bml, g_bml);
    cudaGetSymbolAddress((void**)&aiwh, g_aiwh); cudaGetSymbolAddress((void**)&aiwl, g_aiwl);
    cudaGetSymbolAddress((void**)&wpowh, g_wpowh); cudaGetSymbolAddress((void**)&wpowl, g_wpowl);
    cudaGetSymbolAddress((void**)&ath, g_ath);   cudaGetSymbolAddress((void**)&atl, g_atl);
    cudaGetSymbolAddress((void**)&a2th, g_a2th); cudaGetSymbolAddress((void**)&a2tl, g_a2tl);
    cudaGetSymbolAddress((void**)&a4th, g_a4th); cudaGetSymbolAddress((void**)&a4tl, g_a4tl);
    cudaGetSymbolAddress((void**)&hsh, g_hsh);   cudaGetSymbolAddress((void**)&hsl, g_hsl);
    cudaGetSymbolAddress((void**)&hnh, g_hnh);   cudaGetSymbolAddress((void**)&hnl, g_hnl);
    cudaGetSymbolAddress((void**)&x16h, g_x16h);   cudaGetSymbolAddress((void**)&x16l, g_x16l);
    cudaGetSymbolAddress((void**)&hp16h, g_hp16h); cudaGetSymbolAddress((void**)&hp16l, g_hp16l);
    cudaGetSymbolAddress((void**)&wpow16h, g_wpow16h); cudaGetSymbolAddress((void**)&wpow16l, g_wpow16l);
    cudaGetSymbolAddress((void**)&t16h, g_t16h);   cudaGetSymbolAddress((void**)&t16l, g_t16l);
    cudaGetSymbolAddress((void**)&lh16h, g_lh16h); cudaGetSymbolAddress((void**)&lh16l, g_lh16l);
    cudaGetSymbolAddress((void**)&wih16h, g_wih16h); cudaGetSymbolAddress((void**)&wih16l, g_wih16l);
    cudaGetSymbolAddress((void**)&whh16h, g_whh16h); cudaGetSymbolAddress((void**)&whh16l, g_whh16l);
    cudaGetSymbolAddress((void**)&pw16h, g_pw16h);   cudaGetSymbolAddress((void**)&pw16l, g_pw16l);
    cudaGetSymbolAddress((void**)&aot16h, g_aot16h); cudaGetSymbolAddress((void**)&aot16l, g_aot16l);
    cudaGetSymbolAddress((void**)&m16h, g_m16h);     cudaGetSymbolAddress((void**)&m16l, g_m16l);
    cudaGetSymbolAddress((void**)&hs16h, g_hs16h);   cudaGetSymbolAddress((void**)&hs16l, g_hs16l);
    cudaGetSymbolAddress((void**)&hn16h, g_hn16h);   cudaGetSymbolAddress((void**)&hn16l, g_hn16l);
    cudaGetSymbolAddress((void**)&cx16h, g_cx16h);   cudaGetSymbolAddress((void**)&cx16l, g_cx16l);

    cudaFuncSetAttribute(gemm_mma,
        cudaFuncAttributeMaxDynamicSharedMemorySize, SMEM_SZ);
    cudaFuncSetAttribute(chain_kernel,
        cudaFuncAttributeMaxDynamicSharedMemorySize, SMEM_SZ);
    cudaFuncSetAttribute(tail_kernel,
        cudaFuncAttributeMaxDynamicSharedMemorySize, SMEM_SZ);

    const long W2 = (long)DD*DD;
    const long KP = (long)SS*BB*2*DD;

    // ---- K1: split all operands + transposes ----
    {
        STaskSet st = {};
        auto add = [&](int i, const float* s, bf16* h, bf16* l, long n, int hf) {
            st.t[i] = { s, h, l, (int)(n / 2048), hf };
        };
        add(0,  x,        xh,      xl,      (long)BB*DD, 0);
        add(1,  x,        x16h,    x16l,    (long)BB*DD, 1);
        add(2,  h_prev,   hp16h,   hp16l,   (long)BB*DD, 1);
        add(3,  lstm_h,   lh16h,   lh16l,   (long)SS*BB*DD, 1);
        add(4,  dn_w1,    w1h,     w1l,     W2, 0);
        add(5,  Bm,       bmh,     bml,     W2, 0);
        add(6,  lstm_wih, wih16h,  wih16l,  (long)SS*4*W2, 1);
        add(7,  lstm_whh, whh16h,  whh16l,  (long)SS*4*W2, 1);
        add(8,  attn_in_w, aiwh,   aiwl,    3*W2, 0);
        add(9,  proj_w,   pw16h,   pw16l,   5*W2, 1);
        add(10, A,        wpowh,   wpowl,   W2, 0);
        add(11, A,        wpow16h, wpow16l, W2, 1);
        st.ntasks = 12;
        int total = 0;
        for (int i = 0; i < 12; i++) total += st.t[i].blocks;
        prep_kernel<<<total + 512, 256>>>(st, total,
            A, ath, atl, attn_out_w, aot16h, aot16l);
    }

    // ---- K2 (G1, 480 blocks): slow bf16 tasks FIRST (h1|bx, A^2), then fp2 ----
    {
        GTaskSet ts = {};
        GTask t0 = mk_task(xh, xl, DD, w1h, w1l, DD, p_h1, DD, DD, 0, 2, 16);
        t0.bias = dn_b1; t0.Wn2hi = bmh; t0.Wn2lo = bml;
        t0.Cn2 = p_bx; t0.ldCn2 = DD; t0.nsplit = DD;
        ts.t[0] = t0;
        GTask ta = mk_task(wpowh, wpowl, DD, ath, atl, DD, nullptr, DD, DD, 0, 4, 8);
        ta.Chi = wpowh + W2; ta.Clo = wpowl + W2;
        ta.Cthi = a2th; ta.Ctlo = a2tl; ta.ldCt = DD;
        ta.Dhi = wpow16h + W2; ta.Dlo = wpow16l + W2;
        ts.t[1] = ta;
        for (int s = 0; s < SS; s++) {
            ts.t[2+s] = mk_task(x16h, x16l, DD,
                                wih16h + (long)s*4*W2, wih16l + (long)s*4*W2, DD,
                                p_gA + (long)s*BB*4*DD, 4*DD, DD, 0, 2, 32, 1);
            ts.t[5+s] = mk_task(lh16h + (long)s*BB*DD, lh16l + (long)s*BB*DD, DD,
                                whh16h + (long)s*4*W2, whh16l + (long)s*4*W2, DD,
                                p_gB + (long)s*BB*4*DD, 4*DD, DD, 0, 2, 32, 1);
        }
        GTask tm = mk_task(pw16h + 512, pw16l + 512, 5*DD, aot16h, aot16l, DD,
                           nullptr, DD, DD, 0, 4, 8, 1);
        tm.Chi = m16h; tm.Clo = m16l;
        ts.t[8] = tm;
        ts.ntasks = 9;
        gemm_mma<<<480, 256, SMEM_SZ>>>(ts);
    }

    // ---- K3: S1 fused ----
    s1_kernel<<<2304, 256>>>(p_h1, dn_g, dn_beta, dn_w2, dn_b2, p_delta,
                             proj_w, attn_out_b, proj_b, p_pvec,
                             p_gA, p_gB, lstm_bih, lstm_bhh, lstm_c, decays,
                             out_hnew, out_cnew, hnh, hnl, hn16h, hn16l);

    // ---- K4 (G2, 256 blocks): A^3, A^4 (+A4T), kv split-K-2 (bf16) ----
    {
        GTaskSet ts = {};
        GTask t3 = mk_task(wpowh + W2, wpowl + W2, DD, ath, atl, DD,
                           nullptr, DD, DD, 0, 4, 8);
        t3.Chi = wpowh + 2*W2; t3.Clo = wpowl + 2*W2;
        t3.Dhi = wpow16h + 2*W2; t3.Dlo = wpow16l + 2*W2;
        ts.t[0] = t3;
        GTask t4 = mk_task(wpowh + W2, wpowl + W2, DD, a2th, a2tl, DD,
                           nullptr, DD, DD, 0, 4, 8);
        t4.Chi = wpowh + 3*W2; t4.Clo = wpowl + 3*W2;
        t4.Cthi = a4th; t4.Ctlo = a4tl; t4.ldCt = DD;
        t4.Dhi = wpow16h + 3*W2; t4.Dlo = wpow16l + 3*W2;
        ts.t[1] = t4;
        for (int kz = 0; kz < 2; kz++)
            ts.t[2+kz] = mk_task(hnh, hnl, DD, aiwh + W2, aiwl + W2, DD,
                                 p_kvp + (long)kz*KP, 2*DD, 256, kz*256, 6, 16);
        ts.ntasks = 4;
        gemm_mma<<<256, 256, SMEM_SZ>>>(ts);
    }

    // ---- K5 (224 blocks): A^5..A^8 (bf16+dual), hnew proj (fp2, planes 8..13) ----
    {
        GTaskSet ts = {};
        GTask t5 = mk_task(wpowh + 3*W2, wpowl + 3*W2, DD, ath, atl, DD,
                           nullptr, DD, DD, 0, 4, 8);
        t5.Chi = wpowh + 4*W2; t5.Clo = wpowl + 4*W2;
        t5.Dhi = wpow16h + 4*W2; t5.Dlo = wpow16l + 4*W2;
        ts.t[0] = t5;
        GTask t6 = mk_task(wpowh + 3*W2, wpowl + 3*W2, DD, a2th, a2tl, DD,
                           nullptr, DD, DD, 0, 4, 8);
        t6.Chi = wpowh + 5*W2; t6.Clo = wpowl + 5*W2;
        t6.Dhi = wpow16h + 5*W2; t6.Dlo = wpow16l + 5*W2;
        ts.t[1] = t6;
        GTask t7 = mk_task(wpowh + 2*W2, wpowl + 2*W2, DD, a4th, a4tl, DD,
                           nullptr, DD, DD, 0, 4, 8);
        t7.Chi = wpowh + 6*W2; t7.Clo = wpowl + 6*W2;
        t7.Dhi = wpow16h + 6*W2; t7.Dlo = wpow16l + 6*W2;
        ts.t[2] = t7;
        GTask t8 = mk_task(wpowh + 3*W2, wpowl + 3*W2, DD, a4th, a4tl, DD,
                           nullptr, DD, DD, 0, 4, 8);
        t8.Chi = wpowh + 7*W2; t8.Clo = wpowl + 7*W2;
        t8.Dhi = wpow16h + 7*W2; t8.Dlo = wpow16l + 7*W2;
        ts.t[3] = t8;
        int p = 0;
        for (int i = 0; i < SS; i++)
            for (int kz = 0; kz < 2; kz++, p++)
                ts.t[4+p] = mk_task(hn16h + (long)i*BB*DD, hn16l + (long)i*BB*DD, DD,
                                    pw16h + 1024 + i*512, pw16l + 1024 + i*512, 5*DD,
                                    p_part + (long)(8 + p)*BB*DD, DD,
                                    256, kz*256, 2, 8, 1);
        ts.ntasks = 10;
        gemm_mma<<<224, 256, SMEM_SZ>>>(ts);
    }

    // ---- K6: persistent chain (fp16 2-product, split-K-2, 256 blocks) ----
    chain_kernel<<<256, 256, SMEM_SZ>>>(hp16h, hp16l, wpow16h, wpow16l, p_U,
                                        t16h, t16l, p_delta, h_prev, p_bx,
                                        out_hssm, hsh, hsl, hs16h, hs16l);

    // ---- K7: persistent tail ----
    tail_kernel<<<256, 256, SMEM_SZ>>>(hsh, hsl, hs16h, hs16l,
                                       aiwh, aiwl, pw16h, pw16l, m16h, m16l,
                                       p_qp, p_kvp, p_part, attn_in_b,
                                       cx16h, cx16l, p_pvec, proj_g, proj_beta,
                                       out_y);
}